// round 15
// baseline (speedup 1.0000x reference)
#include <cuda_runtime.h>
#include <cuda_fp16.h>
#include <math.h>
#include <stdint.h>

// ---------------- problem constants ----------------
#define SEQ   1024
#define HID   2048
#define NH    16
#define KVH   4
#define HD    128
#define FDIM  7168
#define NEXP  8
#define PADROWS 2560      // 2048 + 8*64 worst-case pad, 64-aligned
#define MTILES  40        // PADROWS/64
#define EPSV  1e-5f
#define SCALE 0.08838834764831845f

// ---------------- device scratch ----------------
__device__ float g_xn  [SEQ*HID];
__device__ float g_q   [SEQ*NH*HD];
__device__ float g_k   [SEQ*KVH*HD];
__device__ float g_v   [SEQ*KVH*HD];
__device__ float g_attn[SEQ*HID];
__device__ float g_x1  [SEQ*HID];
__device__ float g_xn2 [SEQ*HID];
__device__ float g_Hup [(size_t)PADROWS*FDIM];
__device__ float g_Dout[(size_t)PADROWS*HID];
__device__ float g_topw[SEQ*2];
__device__ int   g_topi[SEQ*2];
__device__ int   g_assign[PADROWS];
__device__ int   g_tilee[MTILES];
__device__ int   g_slot[SEQ*2];

// ---------------- fp16 mma helpers ----------------
__device__ __forceinline__ uint32_t smem_u32(const void* p) {
    uint32_t a;
    asm("{ .reg .u64 t; cvta.to.shared.u64 t, %1; cvt.u32.u64 %0, t; }" : "=r"(a) : "l"(p));
    return a;
}
__device__ __forceinline__ uint32_t pack_h2(float x, float y) {
    __half2 h = __floats2half2_rn(x, y);
    return *reinterpret_cast<uint32_t*>(&h);
}
__device__ __forceinline__ void ldsm_x4(uint32_t& r0, uint32_t& r1, uint32_t& r2,
                                        uint32_t& r3, uint32_t addr) {
    asm volatile("ldmatrix.sync.aligned.m8n8.x4.shared.b16 {%0,%1,%2,%3}, [%4];"
                 : "=r"(r0), "=r"(r1), "=r"(r2), "=r"(r3) : "r"(addr));
}
__device__ __forceinline__ void ldsm_x4t(uint32_t& r0, uint32_t& r1, uint32_t& r2,
                                         uint32_t& r3, uint32_t addr) {
    asm volatile("ldmatrix.sync.aligned.m8n8.x4.trans.shared.b16 {%0,%1,%2,%3}, [%4];"
                 : "=r"(r0), "=r"(r1), "=r"(r2), "=r"(r3) : "r"(addr));
}
__device__ __forceinline__ void mma_f16(float* c, uint32_t a0, uint32_t a1,
                                        uint32_t a2, uint32_t a3,
                                        uint32_t b0, uint32_t b1) {
    asm volatile(
        "mma.sync.aligned.m16n8k16.row.col.f32.f16.f16.f32 "
        "{%0,%1,%2,%3}, {%4,%5,%6,%7}, {%8,%9}, {%0,%1,%2,%3};"
        : "+f"(c[0]), "+f"(c[1]), "+f"(c[2]), "+f"(c[3])
        : "r"(a0), "r"(a1), "r"(a2), "r"(a3), "r"(b0), "r"(b1));
}

// A smem: [rows][32 k halves], 64B/row, 16B-chunk swizzle c^=((row>>1)&3)
__device__ __forceinline__ int offA(int row, int k) {
    return row * 64 + ((((k >> 3) ^ (row >> 1)) & 3) << 4) + ((k & 7) << 1);
}
// B smem: [32 k rows][128 n halves], 256B/row, 16B-chunk swizzle c^=(k&7)
__device__ __forceinline__ int offB(int k, int n) {
    return k * 256 + ((((n >> 3) ^ k) & 15) << 4) + ((n & 7) << 1);
}

#define ATB  8192    // 128-row A tile
#define ATB64 4096   // 64-row A tile
#define BTB  8192
#define HG_SMEM   (512 + 2*ATB + 2*BTB)     // qkv (128-row)
#define HG64_SMEM (512 + 2*ATB64 + 2*BTB)   // 25 KB
#define UPG_SMEM  (512 + 2*ATB64 + 4*BTB)   // 41 KB
#define FA_SMEM   (3 * 32768)

// ============ fused QKV: 128-row tiles, 256 thr, warp 64x32 (proven R11 config) ============
__global__ __launch_bounds__(256, 2)
void hgemm_qkv(const float* __restrict__ A,
               const float* __restrict__ qw, const float* __restrict__ kw,
               const float* __restrict__ vw,
               float* __restrict__ qb, float* __restrict__ kb, float* __restrict__ vb)
{
    extern __shared__ char smc[];
    char* sA = smc + 512;
    char* sB = smc + 512 + 2 * ATB;

    const int bx = blockIdx.x;
    const int m0 = blockIdx.y * 128;
    const float* B; float* C; int ldbc, n0;
    if (bx < 16)      { B = qw; C = qb; ldbc = NH * HD;  n0 = bx * 128; }
    else if (bx < 20) { B = kw; C = kb; ldbc = KVH * HD; n0 = (bx - 16) * 128; }
    else              { B = vw; C = vb; ldbc = KVH * HD; n0 = (bx - 20) * 128; }

    const int tid = threadIdx.x, lane = tid & 31, wid = tid >> 5;
    const int wm = wid & 1, wn = wid >> 1;
    const int grp = lane >> 2, qid = lane & 3;

    const uint32_t sAu = smem_u32(sA), sBu = smem_u32(sB);

    int ar[4], ak[4], bk[4], bn[4];
#pragma unroll
    for (int i = 0; i < 4; i++) {
        int idx = i * 256 + tid;
        ar[i] = idx >> 3; ak[i] = (idx & 7) << 2;
        bk[i] = idx >> 5; bn[i] = (idx & 31) << 2;
    }
    const int aRow = lane & 15, aKoff = (lane >> 4) << 3;
    const int lK = lane & 7, mv = lane >> 3;
    const int bKoff = (mv & 1) << 3, bNoff = (mv >> 1) << 3;

    float acc[4][4][4] = {};
    float4 ra[4], rb[4];
    const int nk = HID >> 5;

    auto load_stage = [&](int kt) {
        const int k0 = kt << 5;
#pragma unroll
        for (int i = 0; i < 4; i++) {
            ra[i] = *(const float4*)(A + (size_t)(m0 + ar[i]) * HID + k0 + ak[i]);
            rb[i] = *(const float4*)(B + (size_t)(k0 + bk[i]) * ldbc + n0 + bn[i]);
        }
    };
    auto store_stage = [&](int b) {
        char* Ab = sA + b * ATB;
        char* Bb = sB + b * BTB;
#pragma unroll
        for (int i = 0; i < 4; i++) {
            uint2 va = { pack_h2(ra[i].x, ra[i].y), pack_h2(ra[i].z, ra[i].w) };
            *(uint2*)(Ab + offA(ar[i], ak[i])) = va;
            uint2 vb2 = { pack_h2(rb[i].x, rb[i].y), pack_h2(rb[i].z, rb[i].w) };
            *(uint2*)(Bb + offB(bk[i], bn[i])) = vb2;
        }
    };

    load_stage(0);
    store_stage(0);
    __syncthreads();

    for (int kt = 0; kt < nk; kt++) {
        if (kt + 1 < nk) load_stage(kt + 1);
        const uint32_t aB = sAu + (kt & 1) * ATB;
        const uint32_t bB = sBu + (kt & 1) * BTB;
#pragma unroll
        for (int s = 0; s < 2; s++) {
            uint32_t b[2][4];
#pragma unroll
            for (int g = 0; g < 2; g++)
                ldsm_x4t(b[g][0], b[g][1], b[g][2], b[g][3],
                         bB + offB(s * 16 + bKoff + lK, wn * 32 + g * 16 + bNoff));
#pragma unroll
            for (int i = 0; i < 4; i++) {
                uint32_t a0, a1, a2, a3;
                ldsm_x4(a0, a1, a2, a3,
                        aB + offA(wm * 64 + i * 16 + aRow, s * 16 + aKoff));
                mma_f16(acc[i][0], a0, a1, a2, a3, b[0][0], b[0][1]);
                mma_f16(acc[i][1], a0, a1, a2, a3, b[0][2], b[0][3]);
                mma_f16(acc[i][2], a0, a1, a2, a3, b[1][0], b[1][1]);
                mma_f16(acc[i][3], a0, a1, a2, a3, b[1][2], b[1][3]);
            }
        }
        if (kt + 1 < nk) store_stage((kt + 1) & 1);
        __syncthreads();
    }

#pragma unroll
    for (int i = 0; i < 4; i++) {
#pragma unroll
        for (int j = 0; j < 4; j++) {
            int r0 = m0 + wm * 64 + i * 16 + grp;
            int r1 = r0 + 8;
            int c  = n0 + wn * 32 + j * 8 + qid * 2;
            *(float2*)(C + (size_t)r0 * ldbc + c) = make_float2(acc[i][j][0], acc[i][j][1]);
            *(float2*)(C + (size_t)r1 * ldbc + c) = make_float2(acc[i][j][2], acc[i][j][3]);
        }
    }
}

// ============ hgemm64: block 64x128, 256 thr, 8 warps (2x4), warp 32x32 ============
// C[M,N] = A@B (+Dadd), optional token gather + per-expert B.
__global__ __launch_bounds__(256, 2)
void hgemm64(const float* __restrict__ A, int lda,
             const float* __restrict__ B, int ldb,
             const float* __restrict__ Dadd,
             float* __restrict__ C, int ldc, int K,
             const int* __restrict__ ridx,
             const int* __restrict__ tilee, long long bstride)
{
    extern __shared__ char smc[];
    int* ridx_sm = (int*)smc;
    char* sA = smc + 512;
    char* sB = smc + 512 + 2 * ATB64;

    const int m0 = blockIdx.y * 64, n0 = blockIdx.x * 128;
    if (tilee) {
        int e = tilee[blockIdx.y];
        if (e < 0) return;
        B += (size_t)e * bstride;
    }

    const int tid = threadIdx.x, lane = tid & 31, wid = tid >> 5;
    const int wm = wid & 1, wn = wid >> 1;     // 2x4: 32-row x 32-col warp tiles
    const int grp = lane >> 2, qid = lane & 3;

    if (ridx) {
        if (tid < 64) ridx_sm[tid] = ridx[m0 + tid];
        __syncthreads();
    }

    const uint32_t sAu = smem_u32(sA), sBu = smem_u32(sB);

    int ar[2], ak[2], bk[4], bn[4];
#pragma unroll
    for (int i = 0; i < 2; i++) {
        int idx = i * 256 + tid;
        ar[i] = idx >> 3; ak[i] = (idx & 7) << 2;
    }
#pragma unroll
    for (int i = 0; i < 4; i++) {
        int idx = i * 256 + tid;
        bk[i] = idx >> 5; bn[i] = (idx & 31) << 2;
    }

    const int aRow = lane & 15, aKoff = (lane >> 4) << 3;
    const int lK = lane & 7, mv = lane >> 3;
    const int bKoff = (mv & 1) << 3, bNoff = (mv >> 1) << 3;

    float acc[2][4][4] = {};
    float4 ra[2], rb[4];
    const int nk = K >> 5;

    auto load_stage = [&](int kt) {
        const int k0 = kt << 5;
#pragma unroll
        for (int i = 0; i < 2; i++) {
            if (ridx) {
                int r = ridx_sm[ar[i]];
                ra[i] = (r >= 0) ? *(const float4*)(A + (size_t)r * lda + k0 + ak[i])
                                 : make_float4(0.f, 0.f, 0.f, 0.f);
            } else {
                ra[i] = *(const float4*)(A + (size_t)(m0 + ar[i]) * lda + k0 + ak[i]);
            }
        }
#pragma unroll
        for (int i = 0; i < 4; i++)
            rb[i] = *(const float4*)(B + (size_t)(k0 + bk[i]) * ldb + n0 + bn[i]);
    };
    auto store_stage = [&](int b) {
        char* Ab = sA + b * ATB64;
        char* Bb = sB + b * BTB;
#pragma unroll
        for (int i = 0; i < 2; i++) {
            uint2 va = { pack_h2(ra[i].x, ra[i].y), pack_h2(ra[i].z, ra[i].w) };
            *(uint2*)(Ab + offA(ar[i], ak[i])) = va;
        }
#pragma unroll
        for (int i = 0; i < 4; i++) {
            uint2 vb = { pack_h2(rb[i].x, rb[i].y), pack_h2(rb[i].z, rb[i].w) };
            *(uint2*)(Bb + offB(bk[i], bn[i])) = vb;
        }
    };

    load_stage(0);
    store_stage(0);
    __syncthreads();

    for (int kt = 0; kt < nk; kt++) {
        if (kt + 1 < nk) load_stage(kt + 1);

        const uint32_t aB = sAu + (kt & 1) * ATB64;
        const uint32_t bB = sBu + (kt & 1) * BTB;
#pragma unroll
        for (int s = 0; s < 2; s++) {
            uint32_t b[2][4];
#pragma unroll
            for (int g = 0; g < 2; g++)
                ldsm_x4t(b[g][0], b[g][1], b[g][2], b[g][3],
                         bB + offB(s * 16 + bKoff + lK, wn * 32 + g * 16 + bNoff));
#pragma unroll
            for (int i = 0; i < 2; i++) {
                uint32_t a0, a1, a2, a3;
                ldsm_x4(a0, a1, a2, a3,
                        aB + offA(wm * 32 + i * 16 + aRow, s * 16 + aKoff));
                mma_f16(acc[i][0], a0, a1, a2, a3, b[0][0], b[0][1]);
                mma_f16(acc[i][1], a0, a1, a2, a3, b[0][2], b[0][3]);
                mma_f16(acc[i][2], a0, a1, a2, a3, b[1][0], b[1][1]);
                mma_f16(acc[i][3], a0, a1, a2, a3, b[1][2], b[1][3]);
            }
        }

        if (kt + 1 < nk) store_stage((kt + 1) & 1);
        __syncthreads();
    }

#pragma unroll
    for (int i = 0; i < 2; i++) {
#pragma unroll
        for (int j = 0; j < 4; j++) {
            int r0 = m0 + wm * 32 + i * 16 + grp;
            int r1 = r0 + 8;
            int c  = n0 + wn * 32 + j * 8 + qid * 2;
            float2 v0 = { acc[i][j][0], acc[i][j][1] };
            float2 v1 = { acc[i][j][2], acc[i][j][3] };
            if (Dadd) {
                float2 d0 = *(const float2*)(Dadd + (size_t)r0 * ldc + c);
                float2 d1 = *(const float2*)(Dadd + (size_t)r1 * ldc + c);
                v0.x += d0.x; v0.y += d0.y;
                v1.x += d1.x; v1.y += d1.y;
            }
            *(float2*)(C + (size_t)r0 * ldc + c) = v0;
            *(float2*)(C + (size_t)r1 * ldc + c) = v1;
        }
    }
}

// ============ upgate64: block 64x128, 512 thr, 16 warps (4x4), warp 16x32, dual B ============
__global__ __launch_bounds__(512, 1)
void upgate64(const float* __restrict__ A, int lda,
              const float* __restrict__ B1, const float* __restrict__ B2,
              float* __restrict__ C,
              const int* __restrict__ ridx,
              const int* __restrict__ tilee, long long bstride)
{
    extern __shared__ char smc[];
    int* ridx_sm = (int*)smc;
    char* sA  = smc + 512;
    char* sB1 = smc + 512 + 2 * ATB64;
    char* sB2 = smc + 512 + 2 * ATB64 + 2 * BTB;

    const int m0 = blockIdx.y * 64, n0 = blockIdx.x * 128;
    int e = tilee[blockIdx.y];
    if (e < 0) return;
    B1 += (size_t)e * bstride;
    B2 += (size_t)e * bstride;

    const int tid = threadIdx.x, lane = tid & 31, wid = tid >> 5;
    const int wm = wid & 3, wn = wid >> 2;     // 4x4: 16-row x 32-col warp tiles
    const int grp = lane >> 2, qid = lane & 3;

    if (tid < 64) ridx_sm[tid] = ridx[m0 + tid];
    __syncthreads();

    const uint32_t sAu = smem_u32(sA), sB1u = smem_u32(sB1), sB2u = smem_u32(sB2);

    // A: 512 float4 slots, 1 per thread. B: 1024 slots, 2 per thread.
    const int ar0 = tid >> 3, ak0 = (tid & 7) << 2;
    int bk[2], bn[2];
#pragma unroll
    for (int i = 0; i < 2; i++) {
        int idx = i * 512 + tid;
        bk[i] = idx >> 5; bn[i] = (idx & 31) << 2;
    }

    const int aRow = lane & 15, aKoff = (lane >> 4) << 3;
    const int lK = lane & 7, mv = lane >> 3;
    const int bKoff = (mv & 1) << 3, bNoff = (mv >> 1) << 3;

    float acc1[4][4] = {}, acc2[4][4] = {};
    float4 ra, rb1[2], rb2[2];
    const int nk = HID >> 5;

    auto load_stage = [&](int kt) {
        const int k0 = kt << 5;
        int r = ridx_sm[ar0];
        ra = (r >= 0) ? *(const float4*)(A + (size_t)r * lda + k0 + ak0)
                      : make_float4(0.f, 0.f, 0.f, 0.f);
#pragma unroll
        for (int i = 0; i < 2; i++) {
            rb1[i] = *(const float4*)(B1 + (size_t)(k0 + bk[i]) * FDIM + n0 + bn[i]);
            rb2[i] = *(const float4*)(B2 + (size_t)(k0 + bk[i]) * FDIM + n0 + bn[i]);
        }
    };
    auto store_stage = [&](int b) {
        char* Ab  = sA + b * ATB64;
        char* B1b = sB1 + b * BTB;
        char* B2b = sB2 + b * BTB;
        uint2 va = { pack_h2(ra.x, ra.y), pack_h2(ra.z, ra.w) };
        *(uint2*)(Ab + offA(ar0, ak0)) = va;
#pragma unroll
        for (int i = 0; i < 2; i++) {
            uint2 v1 = { pack_h2(rb1[i].x, rb1[i].y), pack_h2(rb1[i].z, rb1[i].w) };
            *(uint2*)(B1b + offB(bk[i], bn[i])) = v1;
            uint2 v2 = { pack_h2(rb2[i].x, rb2[i].y), pack_h2(rb2[i].z, rb2[i].w) };
            *(uint2*)(B2b + offB(bk[i], bn[i])) = v2;
        }
    };

    load_stage(0);
    store_stage(0);
    __syncthreads();

    for (int kt = 0; kt < nk; kt++) {
        if (kt + 1 < nk) load_stage(kt + 1);

        const uint32_t aB  = sAu + (kt & 1) * ATB64;
        const uint32_t b1B = sB1u + (kt & 1) * BTB;
        const uint32_t b2B = sB2u + (kt & 1) * BTB;
#pragma unroll
        for (int s = 0; s < 2; s++) {
            uint32_t u[2][4], g[2][4];
#pragma unroll
            for (int gg = 0; gg < 2; gg++) {
                int bo = offB(s * 16 + bKoff + lK, wn * 32 + gg * 16 + bNoff);
                ldsm_x4t(u[gg][0], u[gg][1], u[gg][2], u[gg][3], b1B + bo);
                ldsm_x4t(g[gg][0], g[gg][1], g[gg][2], g[gg][3], b2B + bo);
            }
            uint32_t a0, a1, a2, a3;
            ldsm_x4(a0, a1, a2, a3,
                    aB + offA(wm * 16 + aRow, s * 16 + aKoff));
            mma_f16(acc1[0], a0, a1, a2, a3, u[0][0], u[0][1]);
            mma_f16(acc1[1], a0, a1, a2, a3, u[0][2], u[0][3]);
            mma_f16(acc1[2], a0, a1, a2, a3, u[1][0], u[1][1]);
            mma_f16(acc1[3], a0, a1, a2, a3, u[1][2], u[1][3]);
            mma_f16(acc2[0], a0, a1, a2, a3, g[0][0], g[0][1]);
            mma_f16(acc2[1], a0, a1, a2, a3, g[0][2], g[0][3]);
            mma_f16(acc2[2], a0, a1, a2, a3, g[1][0], g[1][1]);
            mma_f16(acc2[3], a0, a1, a2, a3, g[1][2], g[1][3]);
        }

        if (kt + 1 < nk) store_stage((kt + 1) & 1);
        __syncthreads();
    }

#pragma unroll
    for (int j = 0; j < 4; j++) {
        int r0 = m0 + wm * 16 + grp;
        int r1 = r0 + 8;
        int c  = n0 + wn * 32 + j * 8 + qid * 2;
        float uu, gg;
        float2 v0, v1;
        uu = acc1[j][0]; gg = acc2[j][0]; v0.x = (uu / (1.f + expf(-uu))) * gg;
        uu = acc1[j][1]; gg = acc2[j][1]; v0.y = (uu / (1.f + expf(-uu))) * gg;
        uu = acc1[j][2]; gg = acc2[j][2]; v1.x = (uu / (1.f + expf(-uu))) * gg;
        uu = acc1[j][3]; gg = acc2[j][3]; v1.y = (uu / (1.f + expf(-uu))) * gg;
        *(float2*)(C + (size_t)r0 * FDIM + c) = v0;
        *(float2*)(C + (size_t)r1 * FDIM + c) = v1;
    }
}

// ============ flash attention (unchanged from R13) ============
__global__ __launch_bounds__(256, 1)
void attn_flash()
{
    extern __shared__ char smc[];
    char* sQ = smc;
    char* sK = smc + 32768;
    char* sV = smc + 65536;

    const int bx = blockIdx.x, h = blockIdx.y;
    const int m0 = bx * 128;
    const int tid = threadIdx.x, lane = tid & 31, wid = tid >> 5;
    const int grp = lane >> 2, qid = lane & 3;
    const uint32_t sKu = smem_u32(sK), sVu = smem_u32(sV);
    const uint32_t sQu = smem_u32(sQ);

    const int aRow = lane & 15, aKoff = (lane >> 4) << 3;
    const int lK = lane & 7, mv = lane >> 3;
    const int bKoff = (mv & 1) << 3, bNoff = (mv >> 1) << 3;

#pragma unroll
    for (int i = 0; i < 16; i++) {
        int idx = i * 256 + tid;
        int row = idx >> 5;
        int c4  = (idx & 31) << 2;
        float4 v = *(const float4*)(g_q + (size_t)(m0 + row) * (NH * HD) + h * HD + c4);
        uint2 hv = { pack_h2(v.x * SCALE, v.y * SCALE), pack_h2(v.z * SCALE, v.w * SCALE) };
        *(uint2*)(sQ + ((c4 >> 5) << 13) + offA(row, c4 & 31)) = hv;
    }
    __syncthreads();

    uint32_t qa[8][4];
#pragma unroll
    for (int s = 0; s < 8; s++)
        ldsm_x4(qa[s][0], qa[s][1], qa[s][2], qa[s][3],
                sQu + ((s >> 1) << 13) + offA(wid * 16 + aRow, ((s & 1) << 4) + aKoff));

    float O[16][4] = {};
    float mrun0 = -1e30f, mrun1 = -1e30f, l0 = 0.f, l1 = 0.f;

    for (int kt = 0; kt <= bx; kt++) {
        __syncthreads();
#pragma unroll
        for (int i = 0; i < 16; i++) {
            int idx = i * 256 + tid;
            int row = idx >> 5;
            int c4  = (idx & 31) << 2;
            size_t base = (size_t)(kt * 128 + row) * (KVH * HD) + (h >> 2) * HD + c4;
            float4 kv = *(const float4*)(g_k + base);
            uint2 hk = { pack_h2(kv.x, kv.y), pack_h2(kv.z, kv.w) };
            *(uint2*)(sK + ((c4 >> 5) << 13) + offA(row, c4 & 31)) = hk;
            float4 vv = *(const float4*)(g_v + base);
            uint2 hv = { pack_h2(vv.x, vv.y), pack_h2(vv.z, vv.w) };
            *(uint2*)(sV + ((row >> 5) << 13) + offB(row & 31, c4)) = hv;
        }
        __syncthreads();

        float S[16][4] = {};
#pragma unroll
        for (int s = 0; s < 8; s++) {
#pragma unroll
            for (int jg = 0; jg < 8; jg++) {
                uint32_t b0, b1, b2, b3;
                ldsm_x4(b0, b1, b2, b3,
                        sKu + ((s >> 1) << 13) + offA(jg * 16 + aRow, ((s & 1) << 4) + aKoff));
                mma_f16(S[jg * 2],     qa[s][0], qa[s][1], qa[s][2], qa[s][3], b0, b2);
                mma_f16(S[jg * 2 + 1], qa[s][0], qa[s][1], qa[s][2], qa[s][3], b1, b3);
            }
        }

        if (kt == bx) {
            int row0 = wid * 16 + grp, row1 = row0 + 8;
#pragma unroll
            for (int j = 0; j < 16; j++) {
                int colb = j * 8 + qid * 2;
                if (colb     > row0) S[j][0] = -1e30f;
                if (colb + 1 > row0) S[j][1] = -1e30f;
                if (colb     > row1) S[j][2] = -1e30f;
                if (colb + 1 > row1) S[j][3] = -1e30f;
            }
        }

        float tm0 = -1e30f, tm1 = -1e30f;
#pragma unroll
        for (int j = 0; j < 16; j++) {
            tm0 = fmaxf(tm0, fmaxf(S[j][0], S[j][1]));
            tm1 = fmaxf(tm1, fmaxf(S[j][2], S[j][3]));
        }
        tm0 = fmaxf(tm0, __shfl_xor_sync(0xffffffffu, tm0, 1));
        tm0 = fmaxf(tm0, __shfl_xor_sync(0xffffffffu, tm0, 2));
        tm1 = fmaxf(tm1, __shfl_xor_sync(0xffffffffu, tm1, 1));
        tm1 = fmaxf(tm1, __shfl_xor_sync(0xffffffffu, tm1, 2));
        float mn0 = fmaxf(mrun0, tm0), mn1 = fmaxf(mrun1, tm1);
        float al0 = __expf(mrun0 - mn0), al1 = __expf(mrun1 - mn1);
        float s0 = 0.f, s1 = 0.f;
#pragma unroll
        for (int j = 0; j < 16; j++) {
            S[j][0] = __expf(S[j][0] - mn0); s0 += S[j][0];
            S[j][1] = __expf(S[j][1] - mn0); s0 += S[j][1];
            S[j][2] = __expf(S[j][2] - mn1); s1 += S[j][2];
            S[j][3] = __expf(S[j][3] - mn1); s1 += S[j][3];
        }
        s0 += __shfl_xor_sync(0xffffffffu, s0, 1);
        s0 += __shfl_xor_sync(0xffffffffu, s0, 2);
        s1 += __shfl_xor_sync(0xffffffffu, s1, 1);
        s1 += __shfl_xor_sync(0xffffffffu, s1, 2);
        l0 = l0 * al0 + s0; l1 = l1 * al1 + s1;
        mrun0 = mn0; mrun1 = mn1;
#pragma unroll
        for (int j = 0; j < 16; j++) {
            O[j][0] *= al0; O[j][1] *= al0;
            O[j][2] *= al1; O[j][3] *= al1;
        }

        uint32_t pa[8][4];
#pragma unroll
        for (int s = 0; s < 8; s++) {
            pa[s][0] = pack_h2(S[2 * s][0],     S[2 * s][1]);
            pa[s][1] = pack_h2(S[2 * s][2],     S[2 * s][3]);
            pa[s][2] = pack_h2(S[2 * s + 1][0], S[2 * s + 1][1]);
            pa[s][3] = pack_h2(S[2 * s + 1][2], S[2 * s + 1][3]);
        }

#pragma unroll
        for (int s = 0; s < 8; s++) {
#pragma unroll
            for (int g = 0; g < 8; g++) {
                uint32_t b0, b1, b2, b3;
                ldsm_x4t(b0, b1, b2, b3,
                         sVu + ((s >> 1) << 13) +
                         offB(((s & 1) << 4) + bKoff + lK, g * 16 + bNoff));
                mma_f16(O[g * 2],     pa[s][0], pa[s][1], pa[s][2], pa[s][3], b0, b1);
                mma_f16(O[g * 2 + 1], pa[s][0], pa[s][1], pa[s][2], pa[s][3], b2, b3);
            }
        }
    }

    float inv0 = 1.f / l0, inv1 = 1.f / l1;
    int r0 = m0 + wid * 16 + grp, r1 = r0 + 8;
#pragma unroll
    for (int j = 0; j < 16; j++) {
        int c = h * HD + j * 8 + qid * 2;
        *(float2*)(g_attn + (size_t)r0 * HID + c) = make_float2(O[j][0] * inv0, O[j][1] * inv0);
        *(float2*)(g_attn + (size_t)r1 * HID + c) = make_float2(O[j][2] * inv1, O[j][3] * inv1);
    }
}

// ---------------- RMSNorm ----------------
__global__ void rmsnorm_kernel(const float* __restrict__ x, const float* __restrict__ w,
                               float* __restrict__ y)
{
    int t = blockIdx.x;
    const float* xr = x + (size_t)t * HID;
    float ss = 0.f;
    for (int j = threadIdx.x; j < HID; j += 256) { float v = xr[j]; ss += v * v; }
    __shared__ float sm[256];
    sm[threadIdx.x] = ss; __syncthreads();
    for (int o = 128; o > 0; o >>= 1) {
        if (threadIdx.x < o) sm[threadIdx.x] += sm[threadIdx.x + o];
        __syncthreads();
    }
    float inv = rsqrtf(sm[0] / (float)HID + EPSV);
    for (int j = threadIdx.x; j < HID; j += 256)
        y[(size_t)t * HID + j] = w[j] * (xr[j] * inv);
}

// ---------------- RoPE ----------------
__global__ void rope_kernel(const float* __restrict__ cosb, const float* __restrict__ sinb)
{
    int t = blockIdx.x, hh = blockIdx.y, d = threadIdx.x;
    float* p = (hh < NH) ? (g_q + (size_t)t * NH * HD + hh * HD)
                         : (g_k + (size_t)t * KVH * HD + (hh - NH) * HD);
    __shared__ float buf[HD];
    float x = p[d];
    buf[d] = x;
    __syncthreads();
    float rot = (d < HD / 2) ? -buf[d + HD / 2] : buf[d - HD / 2];
    p[d] = x * cosb[t * HD + d] + rot * sinb[t * HD + d];
}

// ---------------- routing ----------------
__global__ void route_kernel(const float* __restrict__ gw)
{
    int t = blockIdx.x, tid = threadIdx.x;
    float acc[8] = {};
    for (int hh = tid; hh < HID; hh += 256) {
        float xv = g_xn2[(size_t)t * HID + hh];
        const float* gr = gw + hh * 8;
        float4 a0 = *(const float4*)gr, a1 = *(const float4*)(gr + 4);
        acc[0] += xv * a0.x; acc[1] += xv * a0.y; acc[2] += xv * a0.z; acc[3] += xv * a0.w;
        acc[4] += xv * a1.x; acc[5] += xv * a1.y; acc[6] += xv * a1.z; acc[7] += xv * a1.w;
    }
#pragma unroll
    for (int o = 16; o > 0; o >>= 1)
#pragma unroll
        for (int e = 0; e < 8; e++)
            acc[e] += __shfl_down_sync(0xffffffffu, acc[e], o);
    __shared__ float sm[8][8];
    int w = tid >> 5, lane = tid & 31;
    if (lane == 0)
#pragma unroll
        for (int e = 0; e < 8; e++) sm[w][e] = acc[e];
    __syncthreads();
    if (tid == 0) {
        float l[8];
        for (int e = 0; e < 8; e++) {
            float s = 0.f;
            for (int ww = 0; ww < 8; ww++) s += sm[ww][e];
            l[e] = s;
        }
        int i0 = 0;
        for (int e = 1; e < 8; e++) if (l[e] > l[i0]) i0 = e;
        int i1 = -1;
        for (int e = 0; e < 8; e++) if (e != i0 && (i1 < 0 || l[e] > l[i1])) i1 = e;
        float p0 = 1.f, p1 = expf(l[i1] - l[i0]);
        float s = p0 + p1;
        g_topi[t * 2] = i0; g_topi[t * 2 + 1] = i1;
        g_topw[t * 2] = p0 / s; g_topw[t * 2 + 1] = p1 / s;
    }
}

// ---------------- grouping: 64-aligned per-expert segments ----------------
__global__ void group_kernel()
{
    int tid = threadIdx.x;
    for (int i = tid; i < PADROWS; i += 256) g_assign[i] = -1;
    if (tid < MTILES) g_tilee[tid] = -1;
    __shared__ int cnt[NEXP], off[NEXP];
    if (tid < NEXP) cnt[tid] = 0;
    __syncthreads();
    for (int a = tid; a < SEQ * 2; a += 256) atomicAdd(&cnt[g_topi[a]], 1);
    __syncthreads();
    if (tid == 0) {
        int cur = 0;
        for (int e = 0; e < NEXP; e++) {
            off[e] = cur;
            int tiles = (cnt[e] + 63) >> 6;
            for (int tt = 0; tt < tiles; tt++) g_tilee[(cur >> 6) + tt] = e;
            cur += tiles * 64;
        }
    }
    __syncthreads();
    int w = tid >> 5, lane = tid & 31;
    if (w < NEXP) {
        int e = w, base = off[e], filled = 0;
        for (int a0 = 0; a0 < SEQ * 2; a0 += 32) {
            int a = a0 + lane;
            int ti = g_topi[a];
            bool match = (ti == e);
            unsigned msk = __ballot_sync(0xffffffffu, match);
            if (match) {
                int rank = __popc(msk & ((1u << lane) - 1u));
                int slot = base + filled + rank;
                g_assign[slot] = a >> 1;
                g_slot[a] = slot;
            }
            filled += __popc(msk);
        }
    }
}

// ---------------- combine ----------------
__global__ void combine_kernel(float* __restrict__ out)
{
    int t = blockIdx.x;
    int s0 = g_slot[t * 2], s1 = g_slot[t * 2 + 1];
    float w0 = g_topw[t * 2], w1 = g_topw[t * 2 + 1];
    for (int j = threadIdx.x; j < HID; j += 256) {
        size_t o = (size_t)t * HID + j;
        out[o] = g_x1[o] + w0 * g_Dout[(size_t)s0 * HID + j]
                         + w1 * g_Dout[(size_t)s1 * HID + j];
    }
}

// ---------------- launch ----------------
extern "C" void kernel_launch(void* const* d_in, const int* in_sizes, int n_in,
                              void* d_out, int out_size)
{
    const float* hidden = (const float*)d_in[0];
    const float* cosb   = (const float*)d_in[1];
    const float* sinb   = (const float*)d_in[2];
    const float* q_w    = (const float*)d_in[5];
    const float* k_w    = (const float*)d_in[6];
    const float* v_w    = (const float*)d_in[7];
    const float* o_w    = (const float*)d_in[8];
    const float* ln1    = (const float*)d_in[9];
    const float* ln2    = (const float*)d_in[10];
    const float* gate_w = (const float*)d_in[11];
    const float* up_w   = (const float*)d_in[12];
    const float* gp_w   = (const float*)d_in[13];
    const float* down_w = (const float*)d_in[14];
    float* out = (float*)d_out;

    cudaFuncSetAttribute(hgemm_qkv,  cudaFuncAttributeMaxDynamicSharedMemorySize, HG_SMEM);
    cudaFuncSetAttribute(hgemm64,    cudaFuncAttributeMaxDynamicSharedMemorySize, HG64_SMEM);
    cudaFuncSetAttribute(upgate64,   cudaFuncAttributeMaxDynamicSharedMemorySize, UPG_SMEM);
    cudaFuncSetAttribute(attn_flash, cudaFuncAttributeMaxDynamicSharedMemorySize, FA_SMEM);

    void *p_xn, *p_q, *p_attn, *p_x1, *p_xn2, *p_hup, *p_dout, *p_assign, *p_tilee;
    cudaGetSymbolAddress(&p_xn, g_xn);
    cudaGetSymbolAddress(&p_q, g_q);
    cudaGetSymbolAddress(&p_attn, g_attn);
    cudaGetSymbolAddress(&p_x1, g_x1);
    cudaGetSymbolAddress(&p_xn2, g_xn2);
    cudaGetSymbolAddress(&p_hup, g_Hup);
    cudaGetSymbolAddress(&p_dout, g_Dout);
    cudaGetSymbolAddress(&p_assign, g_assign);
    cudaGetSymbolAddress(&p_tilee, g_tilee);
    void *p_k, *p_v;
    cudaGetSymbolAddress(&p_k, g_k);
    cudaGetSymbolAddress(&p_v, g_v);

    float* xn   = (float*)p_xn;
    float* qb   = (float*)p_q;
    float* kb   = (float*)p_k;
    float* vb   = (float*)p_v;
    float* at   = (float*)p_attn;
    float* x1   = (float*)p_x1;
    float* xn2  = (float*)p_xn2;
    float* hup  = (float*)p_hup;
    float* dout = (float*)p_dout;
    int* assign = (int*)p_assign;
    int* tilee  = (int*)p_tilee;

    rmsnorm_kernel<<<SEQ, 256>>>(hidden, ln1, xn);
    hgemm_qkv<<<dim3(24, 8), 256, HG_SMEM>>>(xn, q_w, k_w, v_w, qb, kb, vb);
    rope_kernel<<<dim3(SEQ, NH + KVH), HD>>>(cosb, sinb);
    attn_flash<<<dim3(8, NH), 256, FA_SMEM>>>();
    hgemm64<<<dim3(16, 16), 256, HG64_SMEM>>>(at, HID, o_w, HID, hidden,
                                              x1, HID, HID, nullptr, nullptr, 0);
    rmsnorm_kernel<<<SEQ, 256>>>(x1, ln2, xn2);
    route_kernel<<<SEQ, 256>>>(gate_w);
    group_kernel<<<1, 256>>>();
    upgate64<<<dim3(FDIM / 128, MTILES), 512, UPG_SMEM>>>(
        xn2, HID, up_w, gp_w, hup, assign, tilee, (long long)HID * FDIM);
    hgemm64<<<dim3(HID / 128, MTILES), 256, HG64_SMEM>>>(
        hup, FDIM, down_w, HID, nullptr, dout, HID, FDIM,
        nullptr, tilee, (long long)FDIM * HID);
    combine_kernel<<<SEQ, 256>>>(out);
}

// round 16
// speedup vs baseline: 1.0020x; 1.0020x over previous
#include <cuda_runtime.h>
#include <cuda_fp16.h>
#include <math.h>
#include <stdint.h>

// ---------------- problem constants ----------------
#define SEQ   1024
#define HID   2048
#define NH    16
#define KVH   4
#define HD    128
#define FDIM  7168
#define NEXP  8
#define PADROWS 2560      // 2048 + 8*64 worst-case pad, 64-aligned
#define MTILES  40        // PADROWS/64
#define EPSV  1e-5f
#define SCALE 0.08838834764831845f

// ---------------- device scratch ----------------
__device__ float g_xn  [SEQ*HID];
__device__ float g_q   [SEQ*NH*HD];
__device__ float g_k   [SEQ*KVH*HD];
__device__ float g_v   [SEQ*KVH*HD];
__device__ float g_attn[SEQ*HID];
__device__ float g_x1  [SEQ*HID];
__device__ float g_xn2 [SEQ*HID];
__device__ float g_Hup [(size_t)PADROWS*FDIM];
__device__ float g_Dout[(size_t)PADROWS*HID];
__device__ float g_topw[SEQ*2];
__device__ int   g_topi[SEQ*2];
__device__ int   g_assign[PADROWS];
__device__ int   g_tilee[MTILES];
__device__ int   g_slot[SEQ*2];

// ---------------- fp16 mma helpers ----------------
__device__ __forceinline__ uint32_t smem_u32(const void* p) {
    uint32_t a;
    asm("{ .reg .u64 t; cvta.to.shared.u64 t, %1; cvt.u32.u64 %0, t; }" : "=r"(a) : "l"(p));
    return a;
}
__device__ __forceinline__ uint32_t pack_h2(float x, float y) {
    __half2 h = __floats2half2_rn(x, y);
    return *reinterpret_cast<uint32_t*>(&h);
}
__device__ __forceinline__ void ldsm_x4(uint32_t& r0, uint32_t& r1, uint32_t& r2,
                                        uint32_t& r3, uint32_t addr) {
    asm volatile("ldmatrix.sync.aligned.m8n8.x4.shared.b16 {%0,%1,%2,%3}, [%4];"
                 : "=r"(r0), "=r"(r1), "=r"(r2), "=r"(r3) : "r"(addr));
}
__device__ __forceinline__ void ldsm_x4t(uint32_t& r0, uint32_t& r1, uint32_t& r2,
                                         uint32_t& r3, uint32_t addr) {
    asm volatile("ldmatrix.sync.aligned.m8n8.x4.trans.shared.b16 {%0,%1,%2,%3}, [%4];"
                 : "=r"(r0), "=r"(r1), "=r"(r2), "=r"(r3) : "r"(addr));
}
__device__ __forceinline__ void mma_f16(float* c, uint32_t a0, uint32_t a1,
                                        uint32_t a2, uint32_t a3,
                                        uint32_t b0, uint32_t b1) {
    asm volatile(
        "mma.sync.aligned.m16n8k16.row.col.f32.f16.f16.f32 "
        "{%0,%1,%2,%3}, {%4,%5,%6,%7}, {%8,%9}, {%0,%1,%2,%3};"
        : "+f"(c[0]), "+f"(c[1]), "+f"(c[2]), "+f"(c[3])
        : "r"(a0), "r"(a1), "r"(a2), "r"(a3), "r"(b0), "r"(b1));
}

// A smem: [rows][32 k halves], 64B/row, 16B-chunk swizzle c^=((row>>1)&3)
__device__ __forceinline__ int offA(int row, int k) {
    return row * 64 + ((((k >> 3) ^ (row >> 1)) & 3) << 4) + ((k & 7) << 1);
}
// B smem: [32 k rows][128 n halves], 256B/row, 16B-chunk swizzle c^=(k&7)
__device__ __forceinline__ int offB(int k, int n) {
    return k * 256 + ((((n >> 3) ^ k) & 15) << 4) + ((n & 7) << 1);
}

#define ATB  8192    // 128-row A tile
#define ATB64 4096   // 64-row A tile
#define BTB  8192
#define HG_SMEM   (512 + 2*ATB + 2*BTB)     // qkv (128-row)
#define HG64_SMEM (512 + 2*ATB64 + 2*BTB)   // 25 KB
#define UPG_SMEM  (512 + 2*ATB64 + 4*BTB)   // 41 KB
#define FA_SMEM   (3 * 32768)

// ============ fused QKV: 128-row tiles, 256 thr, warp 64x32 (proven R11 config) ============
__global__ __launch_bounds__(256, 2)
void hgemm_qkv(const float* __restrict__ A,
               const float* __restrict__ qw, const float* __restrict__ kw,
               const float* __restrict__ vw,
               float* __restrict__ qb, float* __restrict__ kb, float* __restrict__ vb)
{
    extern __shared__ char smc[];
    char* sA = smc + 512;
    char* sB = smc + 512 + 2 * ATB;

    const int bx = blockIdx.x;
    const int m0 = blockIdx.y * 128;
    const float* B; float* C; int ldbc, n0;
    if (bx < 16)      { B = qw; C = qb; ldbc = NH * HD;  n0 = bx * 128; }
    else if (bx < 20) { B = kw; C = kb; ldbc = KVH * HD; n0 = (bx - 16) * 128; }
    else              { B = vw; C = vb; ldbc = KVH * HD; n0 = (bx - 20) * 128; }

    const int tid = threadIdx.x, lane = tid & 31, wid = tid >> 5;
    const int wm = wid & 1, wn = wid >> 1;
    const int grp = lane >> 2, qid = lane & 3;

    const uint32_t sAu = smem_u32(sA), sBu = smem_u32(sB);

    int ar[4], ak[4], bk[4], bn[4];
#pragma unroll
    for (int i = 0; i < 4; i++) {
        int idx = i * 256 + tid;
        ar[i] = idx >> 3; ak[i] = (idx & 7) << 2;
        bk[i] = idx >> 5; bn[i] = (idx & 31) << 2;
    }
    const int aRow = lane & 15, aKoff = (lane >> 4) << 3;
    const int lK = lane & 7, mv = lane >> 3;
    const int bKoff = (mv & 1) << 3, bNoff = (mv >> 1) << 3;

    float acc[4][4][4] = {};
    float4 ra[4], rb[4];
    const int nk = HID >> 5;

    auto load_stage = [&](int kt) {
        const int k0 = kt << 5;
#pragma unroll
        for (int i = 0; i < 4; i++) {
            ra[i] = *(const float4*)(A + (size_t)(m0 + ar[i]) * HID + k0 + ak[i]);
            rb[i] = *(const float4*)(B + (size_t)(k0 + bk[i]) * ldbc + n0 + bn[i]);
        }
    };
    auto store_stage = [&](int b) {
        char* Ab = sA + b * ATB;
        char* Bb = sB + b * BTB;
#pragma unroll
        for (int i = 0; i < 4; i++) {
            uint2 va = { pack_h2(ra[i].x, ra[i].y), pack_h2(ra[i].z, ra[i].w) };
            *(uint2*)(Ab + offA(ar[i], ak[i])) = va;
            uint2 vb2 = { pack_h2(rb[i].x, rb[i].y), pack_h2(rb[i].z, rb[i].w) };
            *(uint2*)(Bb + offB(bk[i], bn[i])) = vb2;
        }
    };

    load_stage(0);
    store_stage(0);
    __syncthreads();

    for (int kt = 0; kt < nk; kt++) {
        if (kt + 1 < nk) load_stage(kt + 1);
        const uint32_t aB = sAu + (kt & 1) * ATB;
        const uint32_t bB = sBu + (kt & 1) * BTB;
#pragma unroll
        for (int s = 0; s < 2; s++) {
            uint32_t b[2][4];
#pragma unroll
            for (int g = 0; g < 2; g++)
                ldsm_x4t(b[g][0], b[g][1], b[g][2], b[g][3],
                         bB + offB(s * 16 + bKoff + lK, wn * 32 + g * 16 + bNoff));
#pragma unroll
            for (int i = 0; i < 4; i++) {
                uint32_t a0, a1, a2, a3;
                ldsm_x4(a0, a1, a2, a3,
                        aB + offA(wm * 64 + i * 16 + aRow, s * 16 + aKoff));
                mma_f16(acc[i][0], a0, a1, a2, a3, b[0][0], b[0][1]);
                mma_f16(acc[i][1], a0, a1, a2, a3, b[0][2], b[0][3]);
                mma_f16(acc[i][2], a0, a1, a2, a3, b[1][0], b[1][1]);
                mma_f16(acc[i][3], a0, a1, a2, a3, b[1][2], b[1][3]);
            }
        }
        if (kt + 1 < nk) store_stage((kt + 1) & 1);
        __syncthreads();
    }

#pragma unroll
    for (int i = 0; i < 4; i++) {
#pragma unroll
        for (int j = 0; j < 4; j++) {
            int r0 = m0 + wm * 64 + i * 16 + grp;
            int r1 = r0 + 8;
            int c  = n0 + wn * 32 + j * 8 + qid * 2;
            *(float2*)(C + (size_t)r0 * ldbc + c) = make_float2(acc[i][j][0], acc[i][j][1]);
            *(float2*)(C + (size_t)r1 * ldbc + c) = make_float2(acc[i][j][2], acc[i][j][3]);
        }
    }
}

// ============ hgemm64: block 64x128, 256 thr, 8 warps (2x4), warp 32x32 ============
// C[M,N] = A@B (+Dadd), optional token gather + per-expert B.
__global__ __launch_bounds__(256, 2)
void hgemm64(const float* __restrict__ A, int lda,
             const float* __restrict__ B, int ldb,
             const float* __restrict__ Dadd,
             float* __restrict__ C, int ldc, int K,
             const int* __restrict__ ridx,
             const int* __restrict__ tilee, long long bstride)
{
    extern __shared__ char smc[];
    int* ridx_sm = (int*)smc;
    char* sA = smc + 512;
    char* sB = smc + 512 + 2 * ATB64;

    const int m0 = blockIdx.y * 64, n0 = blockIdx.x * 128;
    if (tilee) {
        int e = tilee[blockIdx.y];
        if (e < 0) return;
        B += (size_t)e * bstride;
    }

    const int tid = threadIdx.x, lane = tid & 31, wid = tid >> 5;
    const int wm = wid & 1, wn = wid >> 1;     // 2x4: 32-row x 32-col warp tiles
    const int grp = lane >> 2, qid = lane & 3;

    if (ridx) {
        if (tid < 64) ridx_sm[tid] = ridx[m0 + tid];
        __syncthreads();
    }

    const uint32_t sAu = smem_u32(sA), sBu = smem_u32(sB);

    int ar[2], ak[2], bk[4], bn[4];
#pragma unroll
    for (int i = 0; i < 2; i++) {
        int idx = i * 256 + tid;
        ar[i] = idx >> 3; ak[i] = (idx & 7) << 2;
    }
#pragma unroll
    for (int i = 0; i < 4; i++) {
        int idx = i * 256 + tid;
        bk[i] = idx >> 5; bn[i] = (idx & 31) << 2;
    }

    const int aRow = lane & 15, aKoff = (lane >> 4) << 3;
    const int lK = lane & 7, mv = lane >> 3;
    const int bKoff = (mv & 1) << 3, bNoff = (mv >> 1) << 3;

    float acc[2][4][4] = {};
    float4 ra[2], rb[4];
    const int nk = K >> 5;

    auto load_stage = [&](int kt) {
        const int k0 = kt << 5;
#pragma unroll
        for (int i = 0; i < 2; i++) {
            if (ridx) {
                int r = ridx_sm[ar[i]];
                ra[i] = (r >= 0) ? *(const float4*)(A + (size_t)r * lda + k0 + ak[i])
                                 : make_float4(0.f, 0.f, 0.f, 0.f);
            } else {
                ra[i] = *(const float4*)(A + (size_t)(m0 + ar[i]) * lda + k0 + ak[i]);
            }
        }
#pragma unroll
        for (int i = 0; i < 4; i++)
            rb[i] = *(const float4*)(B + (size_t)(k0 + bk[i]) * ldb + n0 + bn[i]);
    };
    auto store_stage = [&](int b) {
        char* Ab = sA + b * ATB64;
        char* Bb = sB + b * BTB;
#pragma unroll
        for (int i = 0; i < 2; i++) {
            uint2 va = { pack_h2(ra[i].x, ra[i].y), pack_h2(ra[i].z, ra[i].w) };
            *(uint2*)(Ab + offA(ar[i], ak[i])) = va;
        }
#pragma unroll
        for (int i = 0; i < 4; i++) {
            uint2 vb = { pack_h2(rb[i].x, rb[i].y), pack_h2(rb[i].z, rb[i].w) };
            *(uint2*)(Bb + offB(bk[i], bn[i])) = vb;
        }
    };

    load_stage(0);
    store_stage(0);
    __syncthreads();

    for (int kt = 0; kt < nk; kt++) {
        if (kt + 1 < nk) load_stage(kt + 1);

        const uint32_t aB = sAu + (kt & 1) * ATB64;
        const uint32_t bB = sBu + (kt & 1) * BTB;
#pragma unroll
        for (int s = 0; s < 2; s++) {
            uint32_t b[2][4];
#pragma unroll
            for (int g = 0; g < 2; g++)
                ldsm_x4t(b[g][0], b[g][1], b[g][2], b[g][3],
                         bB + offB(s * 16 + bKoff + lK, wn * 32 + g * 16 + bNoff));
#pragma unroll
            for (int i = 0; i < 2; i++) {
                uint32_t a0, a1, a2, a3;
                ldsm_x4(a0, a1, a2, a3,
                        aB + offA(wm * 32 + i * 16 + aRow, s * 16 + aKoff));
                mma_f16(acc[i][0], a0, a1, a2, a3, b[0][0], b[0][1]);
                mma_f16(acc[i][1], a0, a1, a2, a3, b[0][2], b[0][3]);
                mma_f16(acc[i][2], a0, a1, a2, a3, b[1][0], b[1][1]);
                mma_f16(acc[i][3], a0, a1, a2, a3, b[1][2], b[1][3]);
            }
        }

        if (kt + 1 < nk) store_stage((kt + 1) & 1);
        __syncthreads();
    }

#pragma unroll
    for (int i = 0; i < 2; i++) {
#pragma unroll
        for (int j = 0; j < 4; j++) {
            int r0 = m0 + wm * 32 + i * 16 + grp;
            int r1 = r0 + 8;
            int c  = n0 + wn * 32 + j * 8 + qid * 2;
            float2 v0 = { acc[i][j][0], acc[i][j][1] };
            float2 v1 = { acc[i][j][2], acc[i][j][3] };
            if (Dadd) {
                float2 d0 = *(const float2*)(Dadd + (size_t)r0 * ldc + c);
                float2 d1 = *(const float2*)(Dadd + (size_t)r1 * ldc + c);
                v0.x += d0.x; v0.y += d0.y;
                v1.x += d1.x; v1.y += d1.y;
            }
            *(float2*)(C + (size_t)r0 * ldc + c) = v0;
            *(float2*)(C + (size_t)r1 * ldc + c) = v1;
        }
    }
}

// ============ upgate64: block 64x128, 512 thr, 16 warps (4x4), warp 16x32, dual B ============
__global__ __launch_bounds__(512, 1)
void upgate64(const float* __restrict__ A, int lda,
              const float* __restrict__ B1, const float* __restrict__ B2,
              float* __restrict__ C,
              const int* __restrict__ ridx,
              const int* __restrict__ tilee, long long bstride)
{
    extern __shared__ char smc[];
    int* ridx_sm = (int*)smc;
    char* sA  = smc + 512;
    char* sB1 = smc + 512 + 2 * ATB64;
    char* sB2 = smc + 512 + 2 * ATB64 + 2 * BTB;

    const int m0 = blockIdx.y * 64, n0 = blockIdx.x * 128;
    int e = tilee[blockIdx.y];
    if (e < 0) return;
    B1 += (size_t)e * bstride;
    B2 += (size_t)e * bstride;

    const int tid = threadIdx.x, lane = tid & 31, wid = tid >> 5;
    const int wm = wid & 3, wn = wid >> 2;     // 4x4: 16-row x 32-col warp tiles
    const int grp = lane >> 2, qid = lane & 3;

    if (tid < 64) ridx_sm[tid] = ridx[m0 + tid];
    __syncthreads();

    const uint32_t sAu = smem_u32(sA), sB1u = smem_u32(sB1), sB2u = smem_u32(sB2);

    // A: 512 float4 slots, 1 per thread. B: 1024 slots, 2 per thread.
    const int ar0 = tid >> 3, ak0 = (tid & 7) << 2;
    int bk[2], bn[2];
#pragma unroll
    for (int i = 0; i < 2; i++) {
        int idx = i * 512 + tid;
        bk[i] = idx >> 5; bn[i] = (idx & 31) << 2;
    }

    const int aRow = lane & 15, aKoff = (lane >> 4) << 3;
    const int lK = lane & 7, mv = lane >> 3;
    const int bKoff = (mv & 1) << 3, bNoff = (mv >> 1) << 3;

    float acc1[4][4] = {}, acc2[4][4] = {};
    float4 ra, rb1[2], rb2[2];
    const int nk = HID >> 5;

    auto load_stage = [&](int kt) {
        const int k0 = kt << 5;
        int r = ridx_sm[ar0];
        ra = (r >= 0) ? *(const float4*)(A + (size_t)r * lda + k0 + ak0)
                      : make_float4(0.f, 0.f, 0.f, 0.f);
#pragma unroll
        for (int i = 0; i < 2; i++) {
            rb1[i] = *(const float4*)(B1 + (size_t)(k0 + bk[i]) * FDIM + n0 + bn[i]);
            rb2[i] = *(const float4*)(B2 + (size_t)(k0 + bk[i]) * FDIM + n0 + bn[i]);
        }
    };
    auto store_stage = [&](int b) {
        char* Ab  = sA + b * ATB64;
        char* B1b = sB1 + b * BTB;
        char* B2b = sB2 + b * BTB;
        uint2 va = { pack_h2(ra.x, ra.y), pack_h2(ra.z, ra.w) };
        *(uint2*)(Ab + offA(ar0, ak0)) = va;
#pragma unroll
        for (int i = 0; i < 2; i++) {
            uint2 v1 = { pack_h2(rb1[i].x, rb1[i].y), pack_h2(rb1[i].z, rb1[i].w) };
            *(uint2*)(B1b + offB(bk[i], bn[i])) = v1;
            uint2 v2 = { pack_h2(rb2[i].x, rb2[i].y), pack_h2(rb2[i].z, rb2[i].w) };
            *(uint2*)(B2b + offB(bk[i], bn[i])) = v2;
        }
    };

    load_stage(0);
    store_stage(0);
    __syncthreads();

    for (int kt = 0; kt < nk; kt++) {
        if (kt + 1 < nk) load_stage(kt + 1);

        const uint32_t aB  = sAu + (kt & 1) * ATB64;
        const uint32_t b1B = sB1u + (kt & 1) * BTB;
        const uint32_t b2B = sB2u + (kt & 1) * BTB;
#pragma unroll
        for (int s = 0; s < 2; s++) {
            uint32_t u[2][4], g[2][4];
#pragma unroll
            for (int gg = 0; gg < 2; gg++) {
                int bo = offB(s * 16 + bKoff + lK, wn * 32 + gg * 16 + bNoff);
                ldsm_x4t(u[gg][0], u[gg][1], u[gg][2], u[gg][3], b1B + bo);
                ldsm_x4t(g[gg][0], g[gg][1], g[gg][2], g[gg][3], b2B + bo);
            }
            uint32_t a0, a1, a2, a3;
            ldsm_x4(a0, a1, a2, a3,
                    aB + offA(wm * 16 + aRow, s * 16 + aKoff));
            mma_f16(acc1[0], a0, a1, a2, a3, u[0][0], u[0][1]);
            mma_f16(acc1[1], a0, a1, a2, a3, u[0][2], u[0][3]);
            mma_f16(acc1[2], a0, a1, a2, a3, u[1][0], u[1][1]);
            mma_f16(acc1[3], a0, a1, a2, a3, u[1][2], u[1][3]);
            mma_f16(acc2[0], a0, a1, a2, a3, g[0][0], g[0][1]);
            mma_f16(acc2[1], a0, a1, a2, a3, g[0][2], g[0][3]);
            mma_f16(acc2[2], a0, a1, a2, a3, g[1][0], g[1][1]);
            mma_f16(acc2[3], a0, a1, a2, a3, g[1][2], g[1][3]);
        }

        if (kt + 1 < nk) store_stage((kt + 1) & 1);
        __syncthreads();
    }

#pragma unroll
    for (int j = 0; j < 4; j++) {
        int r0 = m0 + wm * 16 + grp;
        int r1 = r0 + 8;
        int c  = n0 + wn * 32 + j * 8 + qid * 2;
        float uu, gg;
        float2 v0, v1;
        uu = acc1[j][0]; gg = acc2[j][0]; v0.x = (uu / (1.f + expf(-uu))) * gg;
        uu = acc1[j][1]; gg = acc2[j][1]; v0.y = (uu / (1.f + expf(-uu))) * gg;
        uu = acc1[j][2]; gg = acc2[j][2]; v1.x = (uu / (1.f + expf(-uu))) * gg;
        uu = acc1[j][3]; gg = acc2[j][3]; v1.y = (uu / (1.f + expf(-uu))) * gg;
        *(float2*)(C + (size_t)r0 * FDIM + c) = v0;
        *(float2*)(C + (size_t)r1 * FDIM + c) = v1;
    }
}

// ============ flash attention (unchanged from R13) ============
__global__ __launch_bounds__(256, 1)
void attn_flash()
{
    extern __shared__ char smc[];
    char* sQ = smc;
    char* sK = smc + 32768;
    char* sV = smc + 65536;

    const int bx = blockIdx.x, h = blockIdx.y;
    const int m0 = bx * 128;
    const int tid = threadIdx.x, lane = tid & 31, wid = tid >> 5;
    const int grp = lane >> 2, qid = lane & 3;
    const uint32_t sKu = smem_u32(sK), sVu = smem_u32(sV);
    const uint32_t sQu = smem_u32(sQ);

    const int aRow = lane & 15, aKoff = (lane >> 4) << 3;
    const int lK = lane & 7, mv = lane >> 3;
    const int bKoff = (mv & 1) << 3, bNoff = (mv >> 1) << 3;

#pragma unroll
    for (int i = 0; i < 16; i++) {
        int idx = i * 256 + tid;
        int row = idx >> 5;
        int c4  = (idx & 31) << 2;
        float4 v = *(const float4*)(g_q + (size_t)(m0 + row) * (NH * HD) + h * HD + c4);
        uint2 hv = { pack_h2(v.x * SCALE, v.y * SCALE), pack_h2(v.z * SCALE, v.w * SCALE) };
        *(uint2*)(sQ + ((c4 >> 5) << 13) + offA(row, c4 & 31)) = hv;
    }
    __syncthreads();

    uint32_t qa[8][4];
#pragma unroll
    for (int s = 0; s < 8; s++)
        ldsm_x4(qa[s][0], qa[s][1], qa[s][2], qa[s][3],
                sQu + ((s >> 1) << 13) + offA(wid * 16 + aRow, ((s & 1) << 4) + aKoff));

    float O[16][4] = {};
    float mrun0 = -1e30f, mrun1 = -1e30f, l0 = 0.f, l1 = 0.f;

    for (int kt = 0; kt <= bx; kt++) {
        __syncthreads();
#pragma unroll
        for (int i = 0; i < 16; i++) {
            int idx = i * 256 + tid;
            int row = idx >> 5;
            int c4  = (idx & 31) << 2;
            size_t base = (size_t)(kt * 128 + row) * (KVH * HD) + (h >> 2) * HD + c4;
            float4 kv = *(const float4*)(g_k + base);
            uint2 hk = { pack_h2(kv.x, kv.y), pack_h2(kv.z, kv.w) };
            *(uint2*)(sK + ((c4 >> 5) << 13) + offA(row, c4 & 31)) = hk;
            float4 vv = *(const float4*)(g_v + base);
            uint2 hv = { pack_h2(vv.x, vv.y), pack_h2(vv.z, vv.w) };
            *(uint2*)(sV + ((row >> 5) << 13) + offB(row & 31, c4)) = hv;
        }
        __syncthreads();

        float S[16][4] = {};
#pragma unroll
        for (int s = 0; s < 8; s++) {
#pragma unroll
            for (int jg = 0; jg < 8; jg++) {
                uint32_t b0, b1, b2, b3;
                ldsm_x4(b0, b1, b2, b3,
                        sKu + ((s >> 1) << 13) + offA(jg * 16 + aRow, ((s & 1) << 4) + aKoff));
                mma_f16(S[jg * 2],     qa[s][0], qa[s][1], qa[s][2], qa[s][3], b0, b2);
                mma_f16(S[jg * 2 + 1], qa[s][0], qa[s][1], qa[s][2], qa[s][3], b1, b3);
            }
        }

        if (kt == bx) {
            int row0 = wid * 16 + grp, row1 = row0 + 8;
#pragma unroll
            for (int j = 0; j < 16; j++) {
                int colb = j * 8 + qid * 2;
                if (colb     > row0) S[j][0] = -1e30f;
                if (colb + 1 > row0) S[j][1] = -1e30f;
                if (colb     > row1) S[j][2] = -1e30f;
                if (colb + 1 > row1) S[j][3] = -1e30f;
            }
        }

        float tm0 = -1e30f, tm1 = -1e30f;
#pragma unroll
        for (int j = 0; j < 16; j++) {
            tm0 = fmaxf(tm0, fmaxf(S[j][0], S[j][1]));
            tm1 = fmaxf(tm1, fmaxf(S[j][2], S[j][3]));
        }
        tm0 = fmaxf(tm0, __shfl_xor_sync(0xffffffffu, tm0, 1));
        tm0 = fmaxf(tm0, __shfl_xor_sync(0xffffffffu, tm0, 2));
        tm1 = fmaxf(tm1, __shfl_xor_sync(0xffffffffu, tm1, 1));
        tm1 = fmaxf(tm1, __shfl_xor_sync(0xffffffffu, tm1, 2));
        float mn0 = fmaxf(mrun0, tm0), mn1 = fmaxf(mrun1, tm1);
        float al0 = __expf(mrun0 - mn0), al1 = __expf(mrun1 - mn1);
        float s0 = 0.f, s1 = 0.f;
#pragma unroll
        for (int j = 0; j < 16; j++) {
            S[j][0] = __expf(S[j][0] - mn0); s0 += S[j][0];
            S[j][1] = __expf(S[j][1] - mn0); s0 += S[j][1];
            S[j][2] = __expf(S[j][2] - mn1); s1 += S[j][2];
            S[j][3] = __expf(S[j][3] - mn1); s1 += S[j][3];
        }
        s0 += __shfl_xor_sync(0xffffffffu, s0, 1);
        s0 += __shfl_xor_sync(0xffffffffu, s0, 2);
        s1 += __shfl_xor_sync(0xffffffffu, s1, 1);
        s1 += __shfl_xor_sync(0xffffffffu, s1, 2);
        l0 = l0 * al0 + s0; l1 = l1 * al1 + s1;
        mrun0 = mn0; mrun1 = mn1;
#pragma unroll
        for (int j = 0; j < 16; j++) {
            O[j][0] *= al0; O[j][1] *= al0;
            O[j][2] *= al1; O[j][3] *= al1;
        }

        uint32_t pa[8][4];
#pragma unroll
        for (int s = 0; s < 8; s++) {
            pa[s][0] = pack_h2(S[2 * s][0],     S[2 * s][1]);
            pa[s][1] = pack_h2(S[2 * s][2],     S[2 * s][3]);
            pa[s][2] = pack_h2(S[2 * s + 1][0], S[2 * s + 1][1]);
            pa[s][3] = pack_h2(S[2 * s + 1][2], S[2 * s + 1][3]);
        }

#pragma unroll
        for (int s = 0; s < 8; s++) {
#pragma unroll
            for (int g = 0; g < 8; g++) {
                uint32_t b0, b1, b2, b3;
                ldsm_x4t(b0, b1, b2, b3,
                         sVu + ((s >> 1) << 13) +
                         offB(((s & 1) << 4) + bKoff + lK, g * 16 + bNoff));
                mma_f16(O[g * 2],     pa[s][0], pa[s][1], pa[s][2], pa[s][3], b0, b1);
                mma_f16(O[g * 2 + 1], pa[s][0], pa[s][1], pa[s][2], pa[s][3], b2, b3);
            }
        }
    }

    float inv0 = 1.f / l0, inv1 = 1.f / l1;
    int r0 = m0 + wid * 16 + grp, r1 = r0 + 8;
#pragma unroll
    for (int j = 0; j < 16; j++) {
        int c = h * HD + j * 8 + qid * 2;
        *(float2*)(g_attn + (size_t)r0 * HID + c) = make_float2(O[j][0] * inv0, O[j][1] * inv0);
        *(float2*)(g_attn + (size_t)r1 * HID + c) = make_float2(O[j][2] * inv1, O[j][3] * inv1);
    }
}

// ---------------- RMSNorm ----------------
__global__ void rmsnorm_kernel(const float* __restrict__ x, const float* __restrict__ w,
                               float* __restrict__ y)
{
    int t = blockIdx.x;
    const float* xr = x + (size_t)t * HID;
    float ss = 0.f;
    for (int j = threadIdx.x; j < HID; j += 256) { float v = xr[j]; ss += v * v; }
    __shared__ float sm[256];
    sm[threadIdx.x] = ss; __syncthreads();
    for (int o = 128; o > 0; o >>= 1) {
        if (threadIdx.x < o) sm[threadIdx.x] += sm[threadIdx.x + o];
        __syncthreads();
    }
    float inv = rsqrtf(sm[0] / (float)HID + EPSV);
    for (int j = threadIdx.x; j < HID; j += 256)
        y[(size_t)t * HID + j] = w[j] * (xr[j] * inv);
}

// ---------------- RoPE ----------------
__global__ void rope_kernel(const float* __restrict__ cosb, const float* __restrict__ sinb)
{
    int t = blockIdx.x, hh = blockIdx.y, d = threadIdx.x;
    float* p = (hh < NH) ? (g_q + (size_t)t * NH * HD + hh * HD)
                         : (g_k + (size_t)t * KVH * HD + (hh - NH) * HD);
    __shared__ float buf[HD];
    float x = p[d];
    buf[d] = x;
    __syncthreads();
    float rot = (d < HD / 2) ? -buf[d + HD / 2] : buf[d - HD / 2];
    p[d] = x * cosb[t * HD + d] + rot * sinb[t * HD + d];
}

// ---------------- routing ----------------
__global__ void route_kernel(const float* __restrict__ gw)
{
    int t = blockIdx.x, tid = threadIdx.x;
    float acc[8] = {};
    for (int hh = tid; hh < HID; hh += 256) {
        float xv = g_xn2[(size_t)t * HID + hh];
        const float* gr = gw + hh * 8;
        float4 a0 = *(const float4*)gr, a1 = *(const float4*)(gr + 4);
        acc[0] += xv * a0.x; acc[1] += xv * a0.y; acc[2] += xv * a0.z; acc[3] += xv * a0.w;
        acc[4] += xv * a1.x; acc[5] += xv * a1.y; acc[6] += xv * a1.z; acc[7] += xv * a1.w;
    }
#pragma unroll
    for (int o = 16; o > 0; o >>= 1)
#pragma unroll
        for (int e = 0; e < 8; e++)
            acc[e] += __shfl_down_sync(0xffffffffu, acc[e], o);
    __shared__ float sm[8][8];
    int w = tid >> 5, lane = tid & 31;
    if (lane == 0)
#pragma unroll
        for (int e = 0; e < 8; e++) sm[w][e] = acc[e];
    __syncthreads();
    if (tid == 0) {
        float l[8];
        for (int e = 0; e < 8; e++) {
            float s = 0.f;
            for (int ww = 0; ww < 8; ww++) s += sm[ww][e];
            l[e] = s;
        }
        int i0 = 0;
        for (int e = 1; e < 8; e++) if (l[e] > l[i0]) i0 = e;
        int i1 = -1;
        for (int e = 0; e < 8; e++) if (e != i0 && (i1 < 0 || l[e] > l[i1])) i1 = e;
        float p0 = 1.f, p1 = expf(l[i1] - l[i0]);
        float s = p0 + p1;
        g_topi[t * 2] = i0; g_topi[t * 2 + 1] = i1;
        g_topw[t * 2] = p0 / s; g_topw[t * 2 + 1] = p1 / s;
    }
}

// ---------------- grouping: 64-aligned per-expert segments ----------------
__global__ void group_kernel()
{
    int tid = threadIdx.x;
    for (int i = tid; i < PADROWS; i += 256) g_assign[i] = -1;
    if (tid < MTILES) g_tilee[tid] = -1;
    __shared__ int cnt[NEXP], off[NEXP];
    if (tid < NEXP) cnt[tid] = 0;
    __syncthreads();
    for (int a = tid; a < SEQ * 2; a += 256) atomicAdd(&cnt[g_topi[a]], 1);
    __syncthreads();
    if (tid == 0) {
        int cur = 0;
        for (int e = 0; e < NEXP; e++) {
            off[e] = cur;
            int tiles = (cnt[e] + 63) >> 6;
            for (int tt = 0; tt < tiles; tt++) g_tilee[(cur >> 6) + tt] = e;
            cur += tiles * 64;
        }
    }
    __syncthreads();
    int w = tid >> 5, lane = tid & 31;
    if (w < NEXP) {
        int e = w, base = off[e], filled = 0;
        for (int a0 = 0; a0 < SEQ * 2; a0 += 32) {
            int a = a0 + lane;
            int ti = g_topi[a];
            bool match = (ti == e);
            unsigned msk = __ballot_sync(0xffffffffu, match);
            if (match) {
                int rank = __popc(msk & ((1u << lane) - 1u));
                int slot = base + filled + rank;
                g_assign[slot] = a >> 1;
                g_slot[a] = slot;
            }
            filled += __popc(msk);
        }
    }
}

// ---------------- combine ----------------
__global__ void combine_kernel(float* __restrict__ out)
{
    int t = blockIdx.x;
    int s0 = g_slot[t * 2], s1 = g_slot[t * 2 + 1];
    float w0 = g_topw[t * 2], w1 = g_topw[t * 2 + 1];
    for (int j = threadIdx.x; j < HID; j += 256) {
        size_t o = (size_t)t * HID + j;
        out[o] = g_x1[o] + w0 * g_Dout[(size_t)s0 * HID + j]
                         + w1 * g_Dout[(size_t)s1 * HID + j];
    }
}

// ---------------- launch ----------------
extern "C" void kernel_launch(void* const* d_in, const int* in_sizes, int n_in,
                              void* d_out, int out_size)
{
    const float* hidden = (const float*)d_in[0];
    const float* cosb   = (const float*)d_in[1];
    const float* sinb   = (const float*)d_in[2];
    const float* q_w    = (const float*)d_in[5];
    const float* k_w    = (const float*)d_in[6];
    const float* v_w    = (const float*)d_in[7];
    const float* o_w    = (const float*)d_in[8];
    const float* ln1    = (const float*)d_in[9];
    const float* ln2    = (const float*)d_in[10];
    const float* gate_w = (const float*)d_in[11];
    const float* up_w   = (const float*)d_in[12];
    const float* gp_w   = (const float*)d_in[13];
    const float* down_w = (const float*)d_in[14];
    float* out = (float*)d_out;

    cudaFuncSetAttribute(hgemm_qkv,  cudaFuncAttributeMaxDynamicSharedMemorySize, HG_SMEM);
    cudaFuncSetAttribute(hgemm64,    cudaFuncAttributeMaxDynamicSharedMemorySize, HG64_SMEM);
    cudaFuncSetAttribute(upgate64,   cudaFuncAttributeMaxDynamicSharedMemorySize, UPG_SMEM);
    cudaFuncSetAttribute(attn_flash, cudaFuncAttributeMaxDynamicSharedMemorySize, FA_SMEM);

    void *p_xn, *p_q, *p_attn, *p_x1, *p_xn2, *p_hup, *p_dout, *p_assign, *p_tilee;
    cudaGetSymbolAddress(&p_xn, g_xn);
    cudaGetSymbolAddress(&p_q, g_q);
    cudaGetSymbolAddress(&p_attn, g_attn);
    cudaGetSymbolAddress(&p_x1, g_x1);
    cudaGetSymbolAddress(&p_xn2, g_xn2);
    cudaGetSymbolAddress(&p_hup, g_Hup);
    cudaGetSymbolAddress(&p_dout, g_Dout);
    cudaGetSymbolAddress(&p_assign, g_assign);
    cudaGetSymbolAddress(&p_tilee, g_tilee);
    void *p_k, *p_v;
    cudaGetSymbolAddress(&p_k, g_k);
    cudaGetSymbolAddress(&p_v, g_v);

    float* xn   = (float*)p_xn;
    float* qb   = (float*)p_q;
    float* kb   = (float*)p_k;
    float* vb   = (float*)p_v;
    float* at   = (float*)p_attn;
    float* x1   = (float*)p_x1;
    float* xn2  = (float*)p_xn2;
    float* hup  = (float*)p_hup;
    float* dout = (float*)p_dout;
    int* assign = (int*)p_assign;
    int* tilee  = (int*)p_tilee;

    rmsnorm_kernel<<<SEQ, 256>>>(hidden, ln1, xn);
    hgemm_qkv<<<dim3(24, 8), 256, HG_SMEM>>>(xn, q_w, k_w, v_w, qb, kb, vb);
    rope_kernel<<<dim3(SEQ, NH + KVH), HD>>>(cosb, sinb);
    attn_flash<<<dim3(8, NH), 256, FA_SMEM>>>();
    hgemm64<<<dim3(16, 16), 256, HG64_SMEM>>>(at, HID, o_w, HID, hidden,
                                              x1, HID, HID, nullptr, nullptr, 0);
    rmsnorm_kernel<<<SEQ, 256>>>(x1, ln2, xn2);
    route_kernel<<<SEQ, 256>>>(gate_w);
    group_kernel<<<1, 256>>>();
    upgate64<<<dim3(FDIM / 128, MTILES), 512, UPG_SMEM>>>(
        xn2, HID, up_w, gp_w, hup, assign, tilee, (long long)HID * FDIM);
    hgemm64<<<dim3(HID / 128, MTILES), 256, HG64_SMEM>>>(
        hup, FDIM, down_w, HID, nullptr, dout, HID, FDIM,
        nullptr, tilee, (long long)FDIM * HID);
    combine_kernel<<<SEQ, 256>>>(out);
}

// round 17
// speedup vs baseline: 1.1684x; 1.1661x over previous
#include <cuda_runtime.h>
#include <cuda_fp16.h>
#include <math.h>
#include <stdint.h>

// ---------------- problem constants ----------------
#define SEQ   1024
#define HID   2048
#define NH    16
#define KVH   4
#define HD    128
#define FDIM  7168
#define NEXP  8
#define PADROWS 3072
#define MTILES  24
#define EPSV  1e-5f
#define SCALE 0.08838834764831845f

// ---------------- device scratch ----------------
__device__ float g_xn  [SEQ*HID];
__device__ float g_q   [SEQ*NH*HD];
__device__ float g_k   [SEQ*KVH*HD];
__device__ float g_v   [SEQ*KVH*HD];
__device__ float g_attn[SEQ*HID];
__device__ float g_x1  [SEQ*HID];
__device__ float g_xn2 [SEQ*HID];
__device__ __half g_Huph[(size_t)PADROWS*FDIM];   // fp16 h = silu(up)*gate (44 MB)
__device__ float g_Dout[(size_t)PADROWS*HID];
__device__ float g_topw[SEQ*2];
__device__ int   g_topi[SEQ*2];
__device__ int   g_assign[PADROWS];
__device__ int   g_tilee[MTILES];
__device__ int   g_slot[SEQ*2];

// ---------------- fp16 mma helpers ----------------
__device__ __forceinline__ uint32_t smem_u32(const void* p) {
    uint32_t a;
    asm("{ .reg .u64 t; cvta.to.shared.u64 t, %1; cvt.u32.u64 %0, t; }" : "=r"(a) : "l"(p));
    return a;
}
__device__ __forceinline__ uint32_t pack_h2(float x, float y) {
    __half2 h = __floats2half2_rn(x, y);
    return *reinterpret_cast<uint32_t*>(&h);
}
__device__ __forceinline__ void ldsm_x4(uint32_t& r0, uint32_t& r1, uint32_t& r2,
                                        uint32_t& r3, uint32_t addr) {
    asm volatile("ldmatrix.sync.aligned.m8n8.x4.shared.b16 {%0,%1,%2,%3}, [%4];"
                 : "=r"(r0), "=r"(r1), "=r"(r2), "=r"(r3) : "r"(addr));
}
__device__ __forceinline__ void ldsm_x4t(uint32_t& r0, uint32_t& r1, uint32_t& r2,
                                         uint32_t& r3, uint32_t addr) {
    asm volatile("ldmatrix.sync.aligned.m8n8.x4.trans.shared.b16 {%0,%1,%2,%3}, [%4];"
                 : "=r"(r0), "=r"(r1), "=r"(r2), "=r"(r3) : "r"(addr));
}
__device__ __forceinline__ void mma_f16(float* c, uint32_t a0, uint32_t a1,
                                        uint32_t a2, uint32_t a3,
                                        uint32_t b0, uint32_t b1) {
    asm volatile(
        "mma.sync.aligned.m16n8k16.row.col.f32.f16.f16.f32 "
        "{%0,%1,%2,%3}, {%4,%5,%6,%7}, {%8,%9}, {%0,%1,%2,%3};"
        : "+f"(c[0]), "+f"(c[1]), "+f"(c[2]), "+f"(c[3])
        : "r"(a0), "r"(a1), "r"(a2), "r"(a3), "r"(b0), "r"(b1));
}

// A smem: [128 rows][32 k halves], 64B/row, 16B-chunk swizzle c^=((row>>1)&3)
__device__ __forceinline__ int offA(int row, int k) {
    return row * 64 + ((((k >> 3) ^ (row >> 1)) & 3) << 4) + ((k & 7) << 1);
}
// B smem: [32 k rows][128 n halves], 256B/row, 16B-chunk swizzle c^=(k&7)
__device__ __forceinline__ int offB(int k, int n) {
    return k * 256 + ((((n >> 3) ^ k) & 15) << 4) + ((n & 7) << 1);
}

#define ATB 8192
#define BTB 8192
#define HG_SMEM  (512 + 2*ATB + 2*BTB)   // 33.3 KB
#define UPG_SMEM (512 + 2*ATB + 4*BTB)   // 49.7 KB
#define FA_SMEM  (3 * 32768)             // 96 KB

// ============ fp16 GEMM (fp32 A): 256 thr, block 128x128, warp 64x32 ============
__global__ __launch_bounds__(256, 2)
void hgemm(const float* __restrict__ A, int lda,
           const float* __restrict__ B, int ldb,
           const float* __restrict__ Dadd,
           float* __restrict__ C, int ldc, int K,
           const int* __restrict__ ridx,
           const int* __restrict__ tilee, long long bstride)
{
    extern __shared__ char smc[];
    int* ridx_sm = (int*)smc;
    char* sA = smc + 512;
    char* sB = smc + 512 + 2 * ATB;

    const int m0 = blockIdx.y * 128, n0 = blockIdx.x * 128;
    if (tilee) {
        int e = tilee[blockIdx.y];
        if (e < 0) return;
        B += (size_t)e * bstride;
    }

    const int tid = threadIdx.x, lane = tid & 31, wid = tid >> 5;
    const int wm = wid & 1, wn = wid >> 1;
    const int grp = lane >> 2, qid = lane & 3;

    if (ridx) {
        if (tid < 128) ridx_sm[tid] = ridx[m0 + tid];
        __syncthreads();
    }

    const uint32_t sAu = smem_u32(sA), sBu = smem_u32(sB);

    int ar[4], ak[4], bk[4], bn[4];
#pragma unroll
    for (int i = 0; i < 4; i++) {
        int idx = i * 256 + tid;
        ar[i] = idx >> 3; ak[i] = (idx & 7) << 2;
        bk[i] = idx >> 5; bn[i] = (idx & 31) << 2;
    }

    const int aRow = lane & 15, aKoff = (lane >> 4) << 3;
    const int lK = lane & 7, mv = lane >> 3;
    const int bKoff = (mv & 1) << 3, bNoff = (mv >> 1) << 3;

    float acc[4][4][4] = {};
    float4 ra[4], rb[4];
    const int nk = K >> 5;

    auto load_stage = [&](int kt) {
        const int k0 = kt << 5;
#pragma unroll
        for (int i = 0; i < 4; i++) {
            if (ridx) {
                int r = ridx_sm[ar[i]];
                ra[i] = (r >= 0) ? *(const float4*)(A + (size_t)r * lda + k0 + ak[i])
                                 : make_float4(0.f, 0.f, 0.f, 0.f);
            } else {
                ra[i] = *(const float4*)(A + (size_t)(m0 + ar[i]) * lda + k0 + ak[i]);
            }
            rb[i] = *(const float4*)(B + (size_t)(k0 + bk[i]) * ldb + n0 + bn[i]);
        }
    };
    auto store_stage = [&](int b) {
        char* Ab = sA + b * ATB;
        char* Bb = sB + b * BTB;
#pragma unroll
        for (int i = 0; i < 4; i++) {
            uint2 va = { pack_h2(ra[i].x, ra[i].y), pack_h2(ra[i].z, ra[i].w) };
            *(uint2*)(Ab + offA(ar[i], ak[i])) = va;
            uint2 vb = { pack_h2(rb[i].x, rb[i].y), pack_h2(rb[i].z, rb[i].w) };
            *(uint2*)(Bb + offB(bk[i], bn[i])) = vb;
        }
    };

    load_stage(0);
    store_stage(0);
    __syncthreads();

    for (int kt = 0; kt < nk; kt++) {
        if (kt + 1 < nk) load_stage(kt + 1);

        const uint32_t aB = sAu + (kt & 1) * ATB;
        const uint32_t bB = sBu + (kt & 1) * BTB;
#pragma unroll
        for (int s = 0; s < 2; s++) {
            uint32_t b[2][4];
#pragma unroll
            for (int g = 0; g < 2; g++)
                ldsm_x4t(b[g][0], b[g][1], b[g][2], b[g][3],
                         bB + offB(s * 16 + bKoff + lK, wn * 32 + g * 16 + bNoff));
#pragma unroll
            for (int i = 0; i < 4; i++) {
                uint32_t a0, a1, a2, a3;
                ldsm_x4(a0, a1, a2, a3,
                        aB + offA(wm * 64 + i * 16 + aRow, s * 16 + aKoff));
                mma_f16(acc[i][0], a0, a1, a2, a3, b[0][0], b[0][1]);
                mma_f16(acc[i][1], a0, a1, a2, a3, b[0][2], b[0][3]);
                mma_f16(acc[i][2], a0, a1, a2, a3, b[1][0], b[1][1]);
                mma_f16(acc[i][3], a0, a1, a2, a3, b[1][2], b[1][3]);
            }
        }

        if (kt + 1 < nk) store_stage((kt + 1) & 1);
        __syncthreads();
    }

#pragma unroll
    for (int i = 0; i < 4; i++) {
#pragma unroll
        for (int j = 0; j < 4; j++) {
            int r0 = m0 + wm * 64 + i * 16 + grp;
            int r1 = r0 + 8;
            int c  = n0 + wn * 32 + j * 8 + qid * 2;
            float2 v0 = { acc[i][j][0], acc[i][j][1] };
            float2 v1 = { acc[i][j][2], acc[i][j][3] };
            if (Dadd) {
                float2 d0 = *(const float2*)(Dadd + (size_t)r0 * ldc + c);
                float2 d1 = *(const float2*)(Dadd + (size_t)r1 * ldc + c);
                v0.x += d0.x; v0.y += d0.y;
                v1.x += d1.x; v1.y += d1.y;
            }
            *(float2*)(C + (size_t)r0 * ldc + c) = v0;
            *(float2*)(C + (size_t)r1 * ldc + c) = v1;
        }
    }
}

// ============ fp16-A GEMM for MoE down: A is __half (g_Huph) ============
__global__ __launch_bounds__(256, 2)
void hgemm_hA(const __half* __restrict__ A, int lda,
              const float* __restrict__ B, int ldb,
              float* __restrict__ C, int ldc, int K,
              const int* __restrict__ tilee, long long bstride)
{
    extern __shared__ char smc[];
    char* sA = smc + 512;
    char* sB = smc + 512 + 2 * ATB;

    const int m0 = blockIdx.y * 128, n0 = blockIdx.x * 128;
    int e = tilee[blockIdx.y];
    if (e < 0) return;
    B += (size_t)e * bstride;

    const int tid = threadIdx.x, lane = tid & 31, wid = tid >> 5;
    const int wm = wid & 1, wn = wid >> 1;
    const int grp = lane >> 2, qid = lane & 3;

    const uint32_t sAu = smem_u32(sA), sBu = smem_u32(sB);

    int ar[4], ak[4], bk[4], bn[4];
#pragma unroll
    for (int i = 0; i < 4; i++) {
        int idx = i * 256 + tid;
        ar[i] = idx >> 3; ak[i] = (idx & 7) << 2;
        bk[i] = idx >> 5; bn[i] = (idx & 31) << 2;
    }

    const int aRow = lane & 15, aKoff = (lane >> 4) << 3;
    const int lK = lane & 7, mv = lane >> 3;
    const int bKoff = (mv & 1) << 3, bNoff = (mv >> 1) << 3;

    float acc[4][4][4] = {};
    uint2 raw[4];
    float4 rb[4];
    const int nk = K >> 5;

    auto load_stage = [&](int kt) {
        const int k0 = kt << 5;
#pragma unroll
        for (int i = 0; i < 4; i++) {
            raw[i] = *(const uint2*)(A + (size_t)(m0 + ar[i]) * lda + k0 + ak[i]);
            rb[i] = *(const float4*)(B + (size_t)(k0 + bk[i]) * ldb + n0 + bn[i]);
        }
    };
    auto store_stage = [&](int b) {
        char* Ab = sA + b * ATB;
        char* Bb = sB + b * BTB;
#pragma unroll
        for (int i = 0; i < 4; i++) {
            *(uint2*)(Ab + offA(ar[i], ak[i])) = raw[i];
            uint2 vb = { pack_h2(rb[i].x, rb[i].y), pack_h2(rb[i].z, rb[i].w) };
            *(uint2*)(Bb + offB(bk[i], bn[i])) = vb;
        }
    };

    load_stage(0);
    store_stage(0);
    __syncthreads();

    for (int kt = 0; kt < nk; kt++) {
        if (kt + 1 < nk) load_stage(kt + 1);

        const uint32_t aB = sAu + (kt & 1) * ATB;
        const uint32_t bB = sBu + (kt & 1) * BTB;
#pragma unroll
        for (int s = 0; s < 2; s++) {
            uint32_t b[2][4];
#pragma unroll
            for (int g = 0; g < 2; g++)
                ldsm_x4t(b[g][0], b[g][1], b[g][2], b[g][3],
                         bB + offB(s * 16 + bKoff + lK, wn * 32 + g * 16 + bNoff));
#pragma unroll
            for (int i = 0; i < 4; i++) {
                uint32_t a0, a1, a2, a3;
                ldsm_x4(a0, a1, a2, a3,
                        aB + offA(wm * 64 + i * 16 + aRow, s * 16 + aKoff));
                mma_f16(acc[i][0], a0, a1, a2, a3, b[0][0], b[0][1]);
                mma_f16(acc[i][1], a0, a1, a2, a3, b[0][2], b[0][3]);
                mma_f16(acc[i][2], a0, a1, a2, a3, b[1][0], b[1][1]);
                mma_f16(acc[i][3], a0, a1, a2, a3, b[1][2], b[1][3]);
            }
        }

        if (kt + 1 < nk) store_stage((kt + 1) & 1);
        __syncthreads();
    }

#pragma unroll
    for (int i = 0; i < 4; i++) {
#pragma unroll
        for (int j = 0; j < 4; j++) {
            int r0 = m0 + wm * 64 + i * 16 + grp;
            int r1 = r0 + 8;
            int c  = n0 + wn * 32 + j * 8 + qid * 2;
            *(float2*)(C + (size_t)r0 * ldc + c) = make_float2(acc[i][j][0], acc[i][j][1]);
            *(float2*)(C + (size_t)r1 * ldc + c) = make_float2(acc[i][j][2], acc[i][j][3]);
        }
    }
}

// ============ fused QKV: one launch, blockIdx.x selects q/k/v ============
__global__ __launch_bounds__(256, 2)
void hgemm_qkv(const float* __restrict__ A,
               const float* __restrict__ qw, const float* __restrict__ kw,
               const float* __restrict__ vw,
               float* __restrict__ qb, float* __restrict__ kb, float* __restrict__ vb)
{
    extern __shared__ char smc[];
    char* sA = smc + 512;
    char* sB = smc + 512 + 2 * ATB;

    const int bx = blockIdx.x;
    const int m0 = blockIdx.y * 128;
    const float* B; float* C; int ldbc, n0;
    if (bx < 16)      { B = qw; C = qb; ldbc = NH * HD;  n0 = bx * 128; }
    else if (bx < 20) { B = kw; C = kb; ldbc = KVH * HD; n0 = (bx - 16) * 128; }
    else              { B = vw; C = vb; ldbc = KVH * HD; n0 = (bx - 20) * 128; }

    const int tid = threadIdx.x, lane = tid & 31, wid = tid >> 5;
    const int wm = wid & 1, wn = wid >> 1;
    const int grp = lane >> 2, qid = lane & 3;

    const uint32_t sAu = smem_u32(sA), sBu = smem_u32(sB);

    int ar[4], ak[4], bk[4], bn[4];
#pragma unroll
    for (int i = 0; i < 4; i++) {
        int idx = i * 256 + tid;
        ar[i] = idx >> 3; ak[i] = (idx & 7) << 2;
        bk[i] = idx >> 5; bn[i] = (idx & 31) << 2;
    }
    const int aRow = lane & 15, aKoff = (lane >> 4) << 3;
    const int lK = lane & 7, mv = lane >> 3;
    const int bKoff = (mv & 1) << 3, bNoff = (mv >> 1) << 3;

    float acc[4][4][4] = {};
    float4 ra[4], rb[4];
    const int nk = HID >> 5;

    auto load_stage = [&](int kt) {
        const int k0 = kt << 5;
#pragma unroll
        for (int i = 0; i < 4; i++) {
            ra[i] = *(const float4*)(A + (size_t)(m0 + ar[i]) * HID + k0 + ak[i]);
            rb[i] = *(const float4*)(B + (size_t)(k0 + bk[i]) * ldbc + n0 + bn[i]);
        }
    };
    auto store_stage = [&](int b) {
        char* Ab = sA + b * ATB;
        char* Bb = sB + b * BTB;
#pragma unroll
        for (int i = 0; i < 4; i++) {
            uint2 va = { pack_h2(ra[i].x, ra[i].y), pack_h2(ra[i].z, ra[i].w) };
            *(uint2*)(Ab + offA(ar[i], ak[i])) = va;
            uint2 vb2 = { pack_h2(rb[i].x, rb[i].y), pack_h2(rb[i].z, rb[i].w) };
            *(uint2*)(Bb + offB(bk[i], bn[i])) = vb2;
        }
    };

    load_stage(0);
    store_stage(0);
    __syncthreads();

    for (int kt = 0; kt < nk; kt++) {
        if (kt + 1 < nk) load_stage(kt + 1);
        const uint32_t aB = sAu + (kt & 1) * ATB;
        const uint32_t bB = sBu + (kt & 1) * BTB;
#pragma unroll
        for (int s = 0; s < 2; s++) {
            uint32_t b[2][4];
#pragma unroll
            for (int g = 0; g < 2; g++)
                ldsm_x4t(b[g][0], b[g][1], b[g][2], b[g][3],
                         bB + offB(s * 16 + bKoff + lK, wn * 32 + g * 16 + bNoff));
#pragma unroll
            for (int i = 0; i < 4; i++) {
                uint32_t a0, a1, a2, a3;
                ldsm_x4(a0, a1, a2, a3,
                        aB + offA(wm * 64 + i * 16 + aRow, s * 16 + aKoff));
                mma_f16(acc[i][0], a0, a1, a2, a3, b[0][0], b[0][1]);
                mma_f16(acc[i][1], a0, a1, a2, a3, b[0][2], b[0][3]);
                mma_f16(acc[i][2], a0, a1, a2, a3, b[1][0], b[1][1]);
                mma_f16(acc[i][3], a0, a1, a2, a3, b[1][2], b[1][3]);
            }
        }
        if (kt + 1 < nk) store_stage((kt + 1) & 1);
        __syncthreads();
    }

#pragma unroll
    for (int i = 0; i < 4; i++) {
#pragma unroll
        for (int j = 0; j < 4; j++) {
            int r0 = m0 + wm * 64 + i * 16 + grp;
            int r1 = r0 + 8;
            int c  = n0 + wn * 32 + j * 8 + qid * 2;
            *(float2*)(C + (size_t)r0 * ldbc + c) = make_float2(acc[i][j][0], acc[i][j][1]);
            *(float2*)(C + (size_t)r1 * ldbc + c) = make_float2(acc[i][j][2], acc[i][j][3]);
        }
    }
}

// ============ fused upgate: 512 thr, block 128x128, warp 32x32, dual B + SiLU -> fp16 ============
__global__ __launch_bounds__(512, 1)
void hgemm_upgate(const float* __restrict__ A, int lda,
                  const float* __restrict__ B1, const float* __restrict__ B2,
                  __half* __restrict__ C,
                  const int* __restrict__ ridx,
                  const int* __restrict__ tilee, long long bstride)
{
    extern __shared__ char smc[];
    int* ridx_sm = (int*)smc;
    char* sA  = smc + 512;
    char* sB1 = smc + 512 + 2 * ATB;
    char* sB2 = smc + 512 + 2 * ATB + 2 * BTB;

    const int m0 = blockIdx.y * 128, n0 = blockIdx.x * 128;
    int e = tilee[blockIdx.y];
    if (e < 0) return;
    B1 += (size_t)e * bstride;
    B2 += (size_t)e * bstride;

    const int tid = threadIdx.x, lane = tid & 31, wid = tid >> 5;
    const int wm = wid & 3, wn = wid >> 2;
    const int grp = lane >> 2, qid = lane & 3;

    if (tid < 128) ridx_sm[tid] = ridx[m0 + tid];
    __syncthreads();

    const uint32_t sAu = smem_u32(sA), sB1u = smem_u32(sB1), sB2u = smem_u32(sB2);

    int ar[2], ak[2], bk[2], bn[2];
#pragma unroll
    for (int i = 0; i < 2; i++) {
        int idx = i * 512 + tid;
        ar[i] = idx >> 3; ak[i] = (idx & 7) << 2;
        bk[i] = idx >> 5; bn[i] = (idx & 31) << 2;
    }

    const int aRow = lane & 15, aKoff = (lane >> 4) << 3;
    const int lK = lane & 7, mv = lane >> 3;
    const int bKoff = (mv & 1) << 3, bNoff = (mv >> 1) << 3;

    float acc1[2][4][4] = {}, acc2[2][4][4] = {};
    float4 ra[2], rb1[2], rb2[2];
    const int nk = HID >> 5;

    auto load_stage = [&](int kt) {
        const int k0 = kt << 5;
#pragma unroll
        for (int i = 0; i < 2; i++) {
            int r = ridx_sm[ar[i]];
            ra[i] = (r >= 0) ? *(const float4*)(A + (size_t)r * lda + k0 + ak[i])
                             : make_float4(0.f, 0.f, 0.f, 0.f);
            rb1[i] = *(const float4*)(B1 + (size_t)(k0 + bk[i]) * FDIM + n0 + bn[i]);
            rb2[i] = *(const float4*)(B2 + (size_t)(k0 + bk[i]) * FDIM + n0 + bn[i]);
        }
    };
    auto store_stage = [&](int b) {
        char* Ab  = sA + b * ATB;
        char* B1b = sB1 + b * BTB;
        char* B2b = sB2 + b * BTB;
#pragma unroll
        for (int i = 0; i < 2; i++) {
            uint2 va = { pack_h2(ra[i].x, ra[i].y), pack_h2(ra[i].z, ra[i].w) };
            *(uint2*)(Ab + offA(ar[i], ak[i])) = va;
            uint2 v1 = { pack_h2(rb1[i].x, rb1[i].y), pack_h2(rb1[i].z, rb1[i].w) };
            *(uint2*)(B1b + offB(bk[i], bn[i])) = v1;
            uint2 v2 = { pack_h2(rb2[i].x, rb2[i].y), pack_h2(rb2[i].z, rb2[i].w) };
            *(uint2*)(B2b + offB(bk[i], bn[i])) = v2;
        }
    };

    load_stage(0);
    store_stage(0);
    __syncthreads();

    for (int kt = 0; kt < nk; kt++) {
        if (kt + 1 < nk) load_stage(kt + 1);

        const uint32_t aB  = sAu + (kt & 1) * ATB;
        const uint32_t b1B = sB1u + (kt & 1) * BTB;
        const uint32_t b2B = sB2u + (kt & 1) * BTB;
#pragma unroll
        for (int s = 0; s < 2; s++) {
            uint32_t u[2][4], g[2][4];
#pragma unroll
            for (int gg = 0; gg < 2; gg++) {
                int bo = offB(s * 16 + bKoff + lK, wn * 32 + gg * 16 + bNoff);
                ldsm_x4t(u[gg][0], u[gg][1], u[gg][2], u[gg][3], b1B + bo);
                ldsm_x4t(g[gg][0], g[gg][1], g[gg][2], g[gg][3], b2B + bo);
            }
#pragma unroll
            for (int i = 0; i < 2; i++) {
                uint32_t a0, a1, a2, a3;
                ldsm_x4(a0, a1, a2, a3,
                        aB + offA(wm * 32 + i * 16 + aRow, s * 16 + aKoff));
                mma_f16(acc1[i][0], a0, a1, a2, a3, u[0][0], u[0][1]);
                mma_f16(acc1[i][1], a0, a1, a2, a3, u[0][2], u[0][3]);
                mma_f16(acc1[i][2], a0, a1, a2, a3, u[1][0], u[1][1]);
                mma_f16(acc1[i][3], a0, a1, a2, a3, u[1][2], u[1][3]);
                mma_f16(acc2[i][0], a0, a1, a2, a3, g[0][0], g[0][1]);
                mma_f16(acc2[i][1], a0, a1, a2, a3, g[0][2], g[0][3]);
                mma_f16(acc2[i][2], a0, a1, a2, a3, g[1][0], g[1][1]);
                mma_f16(acc2[i][3], a0, a1, a2, a3, g[1][2], g[1][3]);
            }
        }

        if (kt + 1 < nk) store_stage((kt + 1) & 1);
        __syncthreads();
    }

#pragma unroll
    for (int i = 0; i < 2; i++) {
#pragma unroll
        for (int j = 0; j < 4; j++) {
            int r0 = m0 + wm * 32 + i * 16 + grp;
            int r1 = r0 + 8;
            int c  = n0 + wn * 32 + j * 8 + qid * 2;
            float uu, gg;
            float h0, h1, h2, h3;
            uu = acc1[i][j][0]; gg = acc2[i][j][0]; h0 = (uu / (1.f + expf(-uu))) * gg;
            uu = acc1[i][j][1]; gg = acc2[i][j][1]; h1 = (uu / (1.f + expf(-uu))) * gg;
            uu = acc1[i][j][2]; gg = acc2[i][j][2]; h2 = (uu / (1.f + expf(-uu))) * gg;
            uu = acc1[i][j][3]; gg = acc2[i][j][3]; h3 = (uu / (1.f + expf(-uu))) * gg;
            *(uint32_t*)(C + (size_t)r0 * FDIM + c) = pack_h2(h0, h1);
            *(uint32_t*)(C + (size_t)r1 * FDIM + c) = pack_h2(h2, h3);
        }
    }
}

// ============ flash attention (unchanged from R13) ============
__global__ __launch_bounds__(256, 1)
void attn_flash()
{
    extern __shared__ char smc[];
    char* sQ = smc;
    char* sK = smc + 32768;
    char* sV = smc + 65536;

    const int bx = blockIdx.x, h = blockIdx.y;
    const int m0 = bx * 128;
    const int tid = threadIdx.x, lane = tid & 31, wid = tid >> 5;
    const int grp = lane >> 2, qid = lane & 3;
    const uint32_t sKu = smem_u32(sK), sVu = smem_u32(sV);
    const uint32_t sQu = smem_u32(sQ);

    const int aRow = lane & 15, aKoff = (lane >> 4) << 3;
    const int lK = lane & 7, mv = lane >> 3;
    const int bKoff = (mv & 1) << 3, bNoff = (mv >> 1) << 3;

#pragma unroll
    for (int i = 0; i < 16; i++) {
        int idx = i * 256 + tid;
        int row = idx >> 5;
        int c4  = (idx & 31) << 2;
        float4 v = *(const float4*)(g_q + (size_t)(m0 + row) * (NH * HD) + h * HD + c4);
        uint2 hv = { pack_h2(v.x * SCALE, v.y * SCALE), pack_h2(v.z * SCALE, v.w * SCALE) };
        *(uint2*)(sQ + ((c4 >> 5) << 13) + offA(row, c4 & 31)) = hv;
    }
    __syncthreads();

    uint32_t qa[8][4];
#pragma unroll
    for (int s = 0; s < 8; s++)
        ldsm_x4(qa[s][0], qa[s][1], qa[s][2], qa[s][3],
                sQu + ((s >> 1) << 13) + offA(wid * 16 + aRow, ((s & 1) << 4) + aKoff));

    float O[16][4] = {};
    float mrun0 = -1e30f, mrun1 = -1e30f, l0 = 0.f, l1 = 0.f;

    for (int kt = 0; kt <= bx; kt++) {
        __syncthreads();
#pragma unroll
        for (int i = 0; i < 16; i++) {
            int idx = i * 256 + tid;
            int row = idx >> 5;
            int c4  = (idx & 31) << 2;
            size_t base = (size_t)(kt * 128 + row) * (KVH * HD) + (h >> 2) * HD + c4;
            float4 kv = *(const float4*)(g_k + base);
            uint2 hk = { pack_h2(kv.x, kv.y), pack_h2(kv.z, kv.w) };
            *(uint2*)(sK + ((c4 >> 5) << 13) + offA(row, c4 & 31)) = hk;
            float4 vv = *(const float4*)(g_v + base);
            uint2 hv = { pack_h2(vv.x, vv.y), pack_h2(vv.z, vv.w) };
            *(uint2*)(sV + ((row >> 5) << 13) + offB(row & 31, c4)) = hv;
        }
        __syncthreads();

        float S[16][4] = {};
#pragma unroll
        for (int s = 0; s < 8; s++) {
#pragma unroll
            for (int jg = 0; jg < 8; jg++) {
                uint32_t b0, b1, b2, b3;
                ldsm_x4(b0, b1, b2, b3,
                        sKu + ((s >> 1) << 13) + offA(jg * 16 + aRow, ((s & 1) << 4) + aKoff));
                mma_f16(S[jg * 2],     qa[s][0], qa[s][1], qa[s][2], qa[s][3], b0, b2);
                mma_f16(S[jg * 2 + 1], qa[s][0], qa[s][1], qa[s][2], qa[s][3], b1, b3);
            }
        }

        if (kt == bx) {
            int row0 = wid * 16 + grp, row1 = row0 + 8;
#pragma unroll
            for (int j = 0; j < 16; j++) {
                int colb = j * 8 + qid * 2;
                if (colb     > row0) S[j][0] = -1e30f;
                if (colb + 1 > row0) S[j][1] = -1e30f;
                if (colb     > row1) S[j][2] = -1e30f;
                if (colb + 1 > row1) S[j][3] = -1e30f;
            }
        }

        float tm0 = -1e30f, tm1 = -1e30f;
#pragma unroll
        for (int j = 0; j < 16; j++) {
            tm0 = fmaxf(tm0, fmaxf(S[j][0], S[j][1]));
            tm1 = fmaxf(tm1, fmaxf(S[j][2], S[j][3]));
        }
        tm0 = fmaxf(tm0, __shfl_xor_sync(0xffffffffu, tm0, 1));
        tm0 = fmaxf(tm0, __shfl_xor_sync(0xffffffffu, tm0, 2));
        tm1 = fmaxf(tm1, __shfl_xor_sync(0xffffffffu, tm1, 1));
        tm1 = fmaxf(tm1, __shfl_xor_sync(0xffffffffu, tm1, 2));
        float mn0 = fmaxf(mrun0, tm0), mn1 = fmaxf(mrun1, tm1);
        float al0 = __expf(mrun0 - mn0), al1 = __expf(mrun1 - mn1);
        float s0 = 0.f, s1 = 0.f;
#pragma unroll
        for (int j = 0; j < 16; j++) {
            S[j][0] = __expf(S[j][0] - mn0); s0 += S[j][0];
            S[j][1] = __expf(S[j][1] - mn0); s0 += S[j][1];
            S[j][2] = __expf(S[j][2] - mn1); s1 += S[j][2];
            S[j][3] = __expf(S[j][3] - mn1); s1 += S[j][3];
        }
        s0 += __shfl_xor_sync(0xffffffffu, s0, 1);
        s0 += __shfl_xor_sync(0xffffffffu, s0, 2);
        s1 += __shfl_xor_sync(0xffffffffu, s1, 1);
        s1 += __shfl_xor_sync(0xffffffffu, s1, 2);
        l0 = l0 * al0 + s0; l1 = l1 * al1 + s1;
        mrun0 = mn0; mrun1 = mn1;
#pragma unroll
        for (int j = 0; j < 16; j++) {
            O[j][0] *= al0; O[j][1] *= al0;
            O[j][2] *= al1; O[j][3] *= al1;
        }

        uint32_t pa[8][4];
#pragma unroll
        for (int s = 0; s < 8; s++) {
            pa[s][0] = pack_h2(S[2 * s][0],     S[2 * s][1]);
            pa[s][1] = pack_h2(S[2 * s][2],     S[2 * s][3]);
            pa[s][2] = pack_h2(S[2 * s + 1][0], S[2 * s + 1][1]);
            pa[s][3] = pack_h2(S[2 * s + 1][2], S[2 * s + 1][3]);
        }

#pragma unroll
        for (int s = 0; s < 8; s++) {
#pragma unroll
            for (int g = 0; g < 8; g++) {
                uint32_t b0, b1, b2, b3;
                ldsm_x4t(b0, b1, b2, b3,
                         sVu + ((s >> 1) << 13) +
                         offB(((s & 1) << 4) + bKoff + lK, g * 16 + bNoff));
                mma_f16(O[g * 2],     pa[s][0], pa[s][1], pa[s][2], pa[s][3], b0, b1);
                mma_f16(O[g * 2 + 1], pa[s][0], pa[s][1], pa[s][2], pa[s][3], b2, b3);
            }
        }
    }

    float inv0 = 1.f / l0, inv1 = 1.f / l1;
    int r0 = m0 + wid * 16 + grp, r1 = r0 + 8;
#pragma unroll
    for (int j = 0; j < 16; j++) {
        int c = h * HD + j * 8 + qid * 2;
        *(float2*)(g_attn + (size_t)r0 * HID + c) = make_float2(O[j][0] * inv0, O[j][1] * inv0);
        *(float2*)(g_attn + (size_t)r1 * HID + c) = make_float2(O[j][2] * inv1, O[j][3] * inv1);
    }
}

// ---------------- RMSNorm ----------------
__global__ void rmsnorm_kernel(const float* __restrict__ x, const float* __restrict__ w,
                               float* __restrict__ y)
{
    int t = blockIdx.x;
    const float* xr = x + (size_t)t * HID;
    float ss = 0.f;
    for (int j = threadIdx.x; j < HID; j += 256) { float v = xr[j]; ss += v * v; }
    __shared__ float sm[256];
    sm[threadIdx.x] = ss; __syncthreads();
    for (int o = 128; o > 0; o >>= 1) {
        if (threadIdx.x < o) sm[threadIdx.x] += sm[threadIdx.x + o];
        __syncthreads();
    }
    float inv = rsqrtf(sm[0] / (float)HID + EPSV);
    for (int j = threadIdx.x; j < HID; j += 256)
        y[(size_t)t * HID + j] = w[j] * (xr[j] * inv);
}

// ---------------- fused RMSNorm2 + routing ----------------
__global__ void rmsnorm_route_kernel(const float* __restrict__ x, const float* __restrict__ w,
                                     float* __restrict__ y, const float* __restrict__ gw)
{
    int t = blockIdx.x, tid = threadIdx.x;
    const float* xr = x + (size_t)t * HID;
    float ss = 0.f;
    for (int j = tid; j < HID; j += 256) { float v = xr[j]; ss += v * v; }
    __shared__ float sm[256];
    sm[tid] = ss; __syncthreads();
    for (int o = 128; o > 0; o >>= 1) {
        if (tid < o) sm[tid] += sm[tid + o];
        __syncthreads();
    }
    float inv = rsqrtf(sm[0] / (float)HID + EPSV);
    __syncthreads();

    float acc[8] = {};
    for (int j = tid; j < HID; j += 256) {
        float xv = w[j] * (xr[j] * inv);
        y[(size_t)t * HID + j] = xv;
        const float* gr = gw + j * 8;
        float4 a0 = *(const float4*)gr, a1 = *(const float4*)(gr + 4);
        acc[0] += xv * a0.x; acc[1] += xv * a0.y; acc[2] += xv * a0.z; acc[3] += xv * a0.w;
        acc[4] += xv * a1.x; acc[5] += xv * a1.y; acc[6] += xv * a1.z; acc[7] += xv * a1.w;
    }
#pragma unroll
    for (int o = 16; o > 0; o >>= 1)
#pragma unroll
        for (int e = 0; e < 8; e++)
            acc[e] += __shfl_down_sync(0xffffffffu, acc[e], o);
    __shared__ float se[8][8];
    int wwid = tid >> 5, lane = tid & 31;
    if (lane == 0)
#pragma unroll
        for (int e = 0; e < 8; e++) se[wwid][e] = acc[e];
    __syncthreads();
    if (tid == 0) {
        float l[8];
        for (int e = 0; e < 8; e++) {
            float s = 0.f;
            for (int ww = 0; ww < 8; ww++) s += se[ww][e];
            l[e] = s;
        }
        int i0 = 0;
        for (int e = 1; e < 8; e++) if (l[e] > l[i0]) i0 = e;
        int i1 = -1;
        for (int e = 0; e < 8; e++) if (e != i0 && (i1 < 0 || l[e] > l[i1])) i1 = e;
        float p0 = 1.f, p1 = expf(l[i1] - l[i0]);
        float s = p0 + p1;
        g_topi[t * 2] = i0; g_topi[t * 2 + 1] = i1;
        g_topw[t * 2] = p0 / s; g_topw[t * 2 + 1] = p1 / s;
    }
}

// ---------------- RoPE ----------------
__global__ void rope_kernel(const float* __restrict__ cosb, const float* __restrict__ sinb)
{
    int t = blockIdx.x, hh = blockIdx.y, d = threadIdx.x;
    float* p = (hh < NH) ? (g_q + (size_t)t * NH * HD + hh * HD)
                         : (g_k + (size_t)t * KVH * HD + (hh - NH) * HD);
    __shared__ float buf[HD];
    float x = p[d];
    buf[d] = x;
    __syncthreads();
    float rot = (d < HD / 2) ? -buf[d + HD / 2] : buf[d - HD / 2];
    p[d] = x * cosb[t * HD + d] + rot * sinb[t * HD + d];
}

// ---------------- grouping: 128-aligned per-expert segments ----------------
__global__ void group_kernel()
{
    int tid = threadIdx.x;
    for (int i = tid; i < PADROWS; i += 256) g_assign[i] = -1;
    if (tid < MTILES) g_tilee[tid] = -1;
    __shared__ int cnt[NEXP], off[NEXP];
    if (tid < NEXP) cnt[tid] = 0;
    __syncthreads();
    for (int a = tid; a < SEQ * 2; a += 256) atomicAdd(&cnt[g_topi[a]], 1);
    __syncthreads();
    if (tid == 0) {
        int cur = 0;
        for (int e = 0; e < NEXP; e++) {
            off[e] = cur;
            int tiles = (cnt[e] + 127) >> 7;
            for (int tt = 0; tt < tiles; tt++) g_tilee[(cur >> 7) + tt] = e;
            cur += tiles * 128;
        }
    }
    __syncthreads();
    int w = tid >> 5, lane = tid & 31;
    if (w < NEXP) {
        int e = w, base = off[e], filled = 0;
        for (int a0 = 0; a0 < SEQ * 2; a0 += 32) {
            int a = a0 + lane;
            int ti = g_topi[a];
            bool match = (ti == e);
            unsigned msk = __ballot_sync(0xffffffffu, match);
            if (match) {
                int rank = __popc(msk & ((1u << lane) - 1u));
                int slot = base + filled + rank;
                g_assign[slot] = a >> 1;
                g_slot[a] = slot;
            }
            filled += __popc(msk);
        }
    }
}

// ---------------- combine ----------------
__global__ void combine_kernel(float* __restrict__ out)
{
    int t = blockIdx.x;
    int s0 = g_slot[t * 2], s1 = g_slot[t * 2 + 1];
    float w0 = g_topw[t * 2], w1 = g_topw[t * 2 + 1];
    for (int j = threadIdx.x; j < HID; j += 256) {
        size_t o = (size_t)t * HID + j;
        out[o] = g_x1[o] + w0 * g_Dout[(size_t)s0 * HID + j]
                         + w1 * g_Dout[(size_t)s1 * HID + j];
    }
}

// ---------------- launch ----------------
extern "C" void kernel_launch(void* const* d_in, const int* in_sizes, int n_in,
                              void* d_out, int out_size)
{
    const float* hidden = (const float*)d_in[0];
    const float* cosb   = (const float*)d_in[1];
    const float* sinb   = (const float*)d_in[2];
    const float* q_w    = (const float*)d_in[5];
    const float* k_w    = (const float*)d_in[6];
    const float* v_w    = (const float*)d_in[7];
    const float* o_w    = (const float*)d_in[8];
    const float* ln1    = (const float*)d_in[9];
    const float* ln2    = (const float*)d_in[10];
    const float* gate_w = (const float*)d_in[11];
    const float* up_w   = (const float*)d_in[12];
    const float* gp_w   = (const float*)d_in[13];
    const float* down_w = (const float*)d_in[14];
    float* out = (float*)d_out;

    cudaFuncSetAttribute(hgemm,        cudaFuncAttributeMaxDynamicSharedMemorySize, HG_SMEM);
    cudaFuncSetAttribute(hgemm_hA,     cudaFuncAttributeMaxDynamicSharedMemorySize, HG_SMEM);
    cudaFuncSetAttribute(hgemm_qkv,    cudaFuncAttributeMaxDynamicSharedMemorySize, HG_SMEM);
    cudaFuncSetAttribute(hgemm_upgate, cudaFuncAttributeMaxDynamicSharedMemorySize, UPG_SMEM);
    cudaFuncSetAttribute(attn_flash,   cudaFuncAttributeMaxDynamicSharedMemorySize, FA_SMEM);

    void *p_xn, *p_q, *p_attn, *p_x1, *p_xn2, *p_hup, *p_dout, *p_assign, *p_tilee;
    cudaGetSymbolAddress(&p_xn, g_xn);
    cudaGetSymbolAddress(&p_q, g_q);
    cudaGetSymbolAddress(&p_attn, g_attn);
    cudaGetSymbolAddress(&p_x1, g_x1);
    cudaGetSymbolAddress(&p_xn2, g_xn2);
    cudaGetSymbolAddress(&p_hup, g_Huph);
    cudaGetSymbolAddress(&p_dout, g_Dout);
    cudaGetSymbolAddress(&p_assign, g_assign);
    cudaGetSymbolAddress(&p_tilee, g_tilee);
    void *p_k, *p_v;
    cudaGetSymbolAddress(&p_k, g_k);
    cudaGetSymbolAddress(&p_v, g_v);

    float* xn   = (float*)p_xn;
    float* qb   = (float*)p_q;
    float* kb   = (float*)p_k;
    float* vb   = (float*)p_v;
    float* at   = (float*)p_attn;
    float* x1   = (float*)p_x1;
    float* xn2  = (float*)p_xn2;
    __half* hup = (__half*)p_hup;
    float* dout = (float*)p_dout;
    int* assign = (int*)p_assign;
    int* tilee  = (int*)p_tilee;

    rmsnorm_kernel<<<SEQ, 256>>>(hidden, ln1, xn);
    hgemm_qkv<<<dim3(24, 8), 256, HG_SMEM>>>(xn, q_w, k_w, v_w, qb, kb, vb);
    rope_kernel<<<dim3(SEQ, NH + KVH), HD>>>(cosb, sinb);
    attn_flash<<<dim3(8, NH), 256, FA_SMEM>>>();
    hgemm<<<dim3(16, 8), 256, HG_SMEM>>>(at, HID, o_w, HID, hidden,
                                         x1, HID, HID, nullptr, nullptr, 0);
    rmsnorm_route_kernel<<<SEQ, 256>>>(x1, ln2, xn2, gate_w);
    group_kernel<<<1, 256>>>();
    hgemm_upgate<<<dim3(FDIM / 128, MTILES), 512, UPG_SMEM>>>(
        xn2, HID, up_w, gp_w, hup, assign, tilee, (long long)HID * FDIM);
    hgemm_hA<<<dim3(16, MTILES), 256, HG_SMEM>>>(
        hup, FDIM, down_w, HID, dout, HID, FDIM,
        tilee, (long long)FDIM * HID);
    combine_kernel<<<SEQ, 256>>>(out);
}